// round 12
// baseline (speedup 1.0000x reference)
#include <cuda_runtime.h>
#include <cuda_fp16.h>
#include <cstdint>

#define IN_F   128
#define HID_F  128
#define OUT_F  64
#define MAX_N  100000
#define MAX_E  1600000

// ---------------- scratch (static device memory; no allocations) ----------------
__device__ float  g_dinv  [MAX_N];
__device__ int    g_cnt   [MAX_N];
__device__ int    g_rowptr[MAX_N + 1];
__device__ int    g_pos   [MAX_N];
__device__ int    g_col   [MAX_E];         // src id per CSR slot (4B)
__device__ unsigned long long g_scanstate[512];   // decoupled-lookback states
__device__ __half g_h0s   [(size_t)MAX_N * HID_F];   // (x @ W1)*dinv      (fp16)
__device__ __half g_aggh  [(size_t)MAX_N * HID_F];   // relu(conv1) / z16  (fp16)
__device__ __half g_h2s   [(size_t)MAX_N * OUT_F];   // (aggh @ W2)*dinv   (fp16)

// ---------------- inline edge-dtype detection (per-warp, no global state) --------
// int64 node ids < 1e5 -> every odd 32-bit word zero; 32-lane ballot decides.
__device__ __forceinline__ int detect_is64(const unsigned* __restrict__ w) {
    int lane = threadIdx.x & 31;
    return __ballot_sync(0xffffffffu, w[2 * lane + 1] != 0u) == 0u;
}

__global__ void count_kernel(const unsigned* __restrict__ w,
                             const void* __restrict__ ei, int E) {
    const int is64 = detect_is64(w);
    int i = blockIdx.x * blockDim.x + threadIdx.x;
    if (i < E) {
        int d = is64 ? (int)((const long long*)ei)[(size_t)E + i]
                     : ((const int*)ei)[(size_t)E + i];
        atomicAdd(&g_cnt[d], 1);
    }
}

// ---------------- single-pass scan (decoupled lookback) + dinv/pos ---------------
__global__ void scan_onepass(int n, int E) {
    __shared__ int sh[256];
    __shared__ int exsh;
    const int tid = threadIdx.x, b = blockIdx.x;
    const int i = b * 256 + tid;
    const int v = (i < n) ? g_cnt[i] : 0;
    sh[tid] = v;
    __syncthreads();
#pragma unroll
    for (int off = 1; off < 256; off <<= 1) {
        int t = (tid >= off) ? sh[tid - off] : 0;
        __syncthreads();
        sh[tid] += t;
        __syncthreads();
    }
    const int incl = sh[tid];
    const int aggregate = sh[255];

    if (tid == 0) {
        unsigned long long packed =
            ((b == 0 ? 2ULL : 1ULL) << 62) | (unsigned long long)(unsigned)aggregate;
        atomicExch(&g_scanstate[b], packed);
        if (b == 0) exsh = 0;
    }
    if (b != 0 && tid < 32) {
        const int lane = tid;
        unsigned long long ex = 0;
        int idx = b - 1;
        while (true) {
            int j = idx - lane;
            unsigned long long sv = (j >= 0) ? atomicAdd(&g_scanstate[j], 0ULL)
                                             : (2ULL << 62);     // virtual prefix 0
            int st = (int)(sv >> 62);
            unsigned pm = __ballot_sync(0xffffffffu, st == 2);
            unsigned im = __ballot_sync(0xffffffffu, st == 0);
            int pv = pm ? (__ffs(pm) - 1) : 32;
            int iv = im ? (__ffs(im) - 1) : 32;
            if (iv < pv) continue;                 // invalid before prefix: retry
            unsigned long long val = sv & 0x3fffffffffffffffULL;
            unsigned long long contrib = (lane <= (pv < 32 ? pv : 31)) ? val : 0;
#pragma unroll
            for (int o = 16; o; o >>= 1)
                contrib += __shfl_down_sync(0xffffffffu, contrib, o);
            contrib = __shfl_sync(0xffffffffu, contrib, 0);
            ex += contrib;
            if (pv < 32) break;
            idx -= 32;
        }
        if (lane == 0) {
            unsigned long long packed =
                (2ULL << 62) | (ex + (unsigned long long)(unsigned)aggregate);
            atomicExch(&g_scanstate[b], packed);
            exsh = (int)ex;
        }
    }
    __syncthreads();
    const int off = exsh;
    if (i < n) {
        int r = off + incl - v;                   // exclusive prefix
        g_rowptr[i] = r;
        g_pos[i] = r;
        g_dinv[i] = rsqrtf((float)v + 1.0f);
    }
    if (i == 0) g_rowptr[n] = E;
}

__global__ void fill_kernel(const unsigned* __restrict__ w,
                            const void* __restrict__ ei, int E) {
    const int is64 = detect_is64(w);
    int i = blockIdx.x * blockDim.x + threadIdx.x;
    if (i < E) {
        int s, d;
        if (is64) {
            s = (int)((const long long*)ei)[i];
            d = (int)((const long long*)ei)[(size_t)E + i];
        } else {
            s = ((const int*)ei)[i];
            d = ((const int*)ei)[(size_t)E + i];
        }
        int idx = atomicAdd(&g_pos[d], 1);
        g_col[idx] = s;
    }
}

// ---------------- FP16 tensor-core GEMM ------------------------------------------
// C[M,NC] = A[M,K] @ W[K,NC] (+bias) (optionally * dinv[row]), fp32 accumulate.
// mma.m16n8k16.f16.f16.f32. 64-row tiles; 8 warps = 2 m-groups x 4 n-groups.
template<int K, int NC, bool A_HALF, bool OUT_HALF, bool BIAS, bool SCALE_OUT>
__global__ void __launch_bounds__(256) gemm_fp16(
        const void* __restrict__ Av, const float* __restrict__ W,
        const float* __restrict__ bias, void* __restrict__ Cv, int M) {
    constexpr int KP2  = K / 2 + 4;
    constexpr int NCP2 = NC + 8;
    constexpr int NT_W = NC / 32;

    extern __shared__ unsigned sh[];
    unsigned* Ws2 = sh;                       // (K/2) * NCP2 words
    unsigned* As2 = sh + (K / 2) * NCP2;      // 64 * KP2 words

    const int tid = threadIdx.x;

    for (int i = tid; i < (K / 2) * (NC / 4); i += 256) {
        int kp = i / (NC / 4), n4 = i - kp * (NC / 4);
        float4 r0 = *(const float4*)(W + (size_t)(2 * kp) * NC + n4 * 4);
        float4 r1 = *(const float4*)(W + (size_t)(2 * kp + 1) * NC + n4 * 4);
        uint4 u;
        *(__half2*)&u.x = __floats2half2_rn(r0.x, r1.x);
        *(__half2*)&u.y = __floats2half2_rn(r0.y, r1.y);
        *(__half2*)&u.z = __floats2half2_rn(r0.z, r1.z);
        *(__half2*)&u.w = __floats2half2_rn(r0.w, r1.w);
        *(uint4*)(Ws2 + kp * NCP2 + n4 * 4) = u;
    }

    const int warp = tid >> 5, lane = tid & 31;
    const int g = lane >> 2, tg = lane & 3;
    const int mi = warp >> 2;
    const int ni = warp & 3;
    const int ntiles = (M + 63) >> 6;

    for (int tile = blockIdx.x; tile < ntiles; tile += gridDim.x) {
        const int row0 = tile << 6;
        __syncthreads();
        constexpr int K8 = K / 8;
        for (int i = tid; i < 64 * K8; i += 256) {
            int r = i / K8, c8 = i - r * K8;
            uint4 u;
            if (A_HALF) {
                const __half* A = (const __half*)Av;
                if (row0 + r < M)
                    u = *(const uint4*)(A + (size_t)(row0 + r) * K + c8 * 8);
                else
                    u = make_uint4(0, 0, 0, 0);
            } else {
                const float* A = (const float*)Av;
                float4 v0 = {0.f, 0.f, 0.f, 0.f}, v1 = {0.f, 0.f, 0.f, 0.f};
                if (row0 + r < M) {
                    v0 = *(const float4*)(A + (size_t)(row0 + r) * K + c8 * 8);
                    v1 = *(const float4*)(A + (size_t)(row0 + r) * K + c8 * 8 + 4);
                }
                *(__half2*)&u.x = __floats2half2_rn(v0.x, v0.y);
                *(__half2*)&u.y = __floats2half2_rn(v0.z, v0.w);
                *(__half2*)&u.z = __floats2half2_rn(v1.x, v1.y);
                *(__half2*)&u.w = __floats2half2_rn(v1.z, v1.w);
            }
            *(uint4*)(As2 + r * KP2 + c8 * 4) = u;
        }
        __syncthreads();

        float acc[2][NT_W][4];
#pragma unroll
        for (int ms = 0; ms < 2; ms++)
#pragma unroll
            for (int t = 0; t < NT_W; t++)
#pragma unroll
                for (int v = 0; v < 4; v++) acc[ms][t][v] = 0.f;

        const unsigned* Arow0 = As2 + (mi * 32 + g) * KP2;
        const unsigned* Arow1 = Arow0 + 16 * KP2;
#pragma unroll
        for (int kp0 = 0; kp0 < K / 2; kp0 += 8) {
            unsigned a[2][4];
            a[0][0] = Arow0[kp0 + tg];
            a[0][1] = Arow0[8 * KP2 + kp0 + tg];
            a[0][2] = Arow0[kp0 + tg + 4];
            a[0][3] = Arow0[8 * KP2 + kp0 + tg + 4];
            a[1][0] = Arow1[kp0 + tg];
            a[1][1] = Arow1[8 * KP2 + kp0 + tg];
            a[1][2] = Arow1[kp0 + tg + 4];
            a[1][3] = Arow1[8 * KP2 + kp0 + tg + 4];
#pragma unroll
            for (int t = 0; t < NT_W; t++) {
                int n0 = ni * (NT_W * 8) + t * 8;
                unsigned b0 = Ws2[(kp0 + tg) * NCP2 + n0 + g];
                unsigned b1 = Ws2[(kp0 + tg + 4) * NCP2 + n0 + g];
#pragma unroll
                for (int ms = 0; ms < 2; ms++) {
                    asm volatile(
                        "mma.sync.aligned.m16n8k16.row.col.f32.f16.f16.f32 "
                        "{%0,%1,%2,%3},{%4,%5,%6,%7},{%8,%9},{%0,%1,%2,%3};\n"
                        : "+f"(acc[ms][t][0]), "+f"(acc[ms][t][1]),
                          "+f"(acc[ms][t][2]), "+f"(acc[ms][t][3])
                        : "r"(a[ms][0]), "r"(a[ms][1]), "r"(a[ms][2]), "r"(a[ms][3]),
                          "r"(b0), "r"(b1));
                }
            }
        }

#pragma unroll
        for (int ms = 0; ms < 2; ms++) {
            const int r0 = row0 + mi * 32 + ms * 16 + g;
            const int r1 = r0 + 8;
            float s0 = 1.f, s1 = 1.f;
            if (SCALE_OUT) {
                if (r0 < M) s0 = g_dinv[r0];
                if (r1 < M) s1 = g_dinv[r1];
            }
#pragma unroll
            for (int t = 0; t < NT_W; t++) {
                int n0 = ni * (NT_W * 8) + t * 8 + 2 * tg;
                float bx = 0.f, by = 0.f;
                if (BIAS) { bx = bias[n0]; by = bias[n0 + 1]; }
                if (OUT_HALF) {
                    __half* C = (__half*)Cv;
                    if (r0 < M)
                        *(__half2*)(C + (size_t)r0 * NC + n0) = __floats2half2_rn(
                            (acc[ms][t][0] + bx) * s0, (acc[ms][t][1] + by) * s0);
                    if (r1 < M)
                        *(__half2*)(C + (size_t)r1 * NC + n0) = __floats2half2_rn(
                            (acc[ms][t][2] + bx) * s1, (acc[ms][t][3] + by) * s1);
                } else {
                    float* C = (float*)Cv;
                    if (r0 < M) {
                        float2 o = {(acc[ms][t][0] + bx) * s0, (acc[ms][t][1] + by) * s0};
                        *(float2*)(C + (size_t)r0 * NC + n0) = o;
                    }
                    if (r1 < M) {
                        float2 o = {(acc[ms][t][2] + bx) * s1, (acc[ms][t][3] + by) * s1};
                        *(float2*)(C + (size_t)r1 * NC + n0) = o;
                    }
                }
            }
        }
    }
}

// ------------- CSR gather over pre-scaled features (warp per destination row) ---
// hs[i] = h[i]*dinv[i] (fp16). out[i] = dv*(sum_nbr hs[s] + hs[i]) + bias ; relu?
// OUT_MODE: 0 = fp16 out ; 1 = fp32 out ; 2 = fp32 out + fp16 copy (out16)
template<int F, bool RELU, int OUT_MODE>
__global__ void __launch_bounds__(256) gather_agg(
        const __half* __restrict__ hs, const float* __restrict__ bias,
        void* __restrict__ out, __half* __restrict__ out16, int Nn) {
    int w = (blockIdx.x * 256 + threadIdx.x) >> 5;
    int lane = threadIdx.x & 31;
    if (w >= Nn) return;
    constexpr int V = F / 32;               // halves per lane: 4 or 2

    float dv = g_dinv[w];
    float acc[V];

    {
        const __half* hp = hs + (size_t)w * F + lane * V;
        if (V == 4) {
            uint2 u = *(const uint2*)hp;
            float2 f0 = __half22float2(*(const __half2*)&u.x);
            float2 f1 = __half22float2(*(const __half2*)&u.y);
            acc[0] = f0.x; acc[1] = f0.y; acc[2] = f1.x; acc[3] = f1.y;
        } else {
            unsigned u = *(const unsigned*)hp;
            float2 f0 = __half22float2(*(const __half2*)&u);
            acc[0] = f0.x; acc[1] = f0.y;
        }
    }

    int beg = g_rowptr[w], end = g_rowptr[w + 1];
#pragma unroll 8
    for (int j = beg; j < end; j++) {
        int s = g_col[j];                   // 4B warp-uniform broadcast load
        const __half* hp = hs + (size_t)s * F + lane * V;
        if (V == 4) {
            uint2 u = *(const uint2*)hp;
            float2 f0 = __half22float2(*(const __half2*)&u.x);
            float2 f1 = __half22float2(*(const __half2*)&u.y);
            acc[0] += f0.x; acc[1] += f0.y; acc[2] += f1.x; acc[3] += f1.y;
        } else {
            unsigned u = *(const unsigned*)hp;
            float2 f0 = __half22float2(*(const __half2*)&u);
            acc[0] += f0.x; acc[1] += f0.y;
        }
    }

    float res[V];
#pragma unroll
    for (int v = 0; v < V; v++) {
        res[v] = fmaf(acc[v], dv, bias[lane * V + v]);
        if (RELU) res[v] = fmaxf(res[v], 0.f);
    }

    if (OUT_MODE == 0) {
        __half* op = (__half*)out + (size_t)w * F + lane * V;
        if (V == 4) {
            uint2 u;
            *(__half2*)&u.x = __floats2half2_rn(res[0], res[1]);
            *(__half2*)&u.y = __floats2half2_rn(res[2], res[3]);
            *(uint2*)op = u;
        } else {
            *(__half2*)op = __floats2half2_rn(res[0], res[1]);
        }
    } else {
        float* op = (float*)out + (size_t)w * F + lane * V;
        if (V == 4) { float4 o = {res[0], res[1], res[2], res[3]}; *(float4*)op = o; }
        else        { float2 o = {res[0], res[1]};                 *(float2*)op = o; }
        if (OUT_MODE == 2) {
            __half* op16 = out16 + (size_t)w * F + lane * V;
            if (V == 4) {
                uint2 u;
                *(__half2*)&u.x = __floats2half2_rn(res[0], res[1]);
                *(__half2*)&u.y = __floats2half2_rn(res[2], res[3]);
                *(uint2*)op16 = u;
            } else {
                *(__half2*)op16 = __floats2half2_rn(res[0], res[1]);
            }
        }
    }
}

// --------------------------------- launch ---------------------------------------
extern "C" void kernel_launch(void* const* d_in, const int* in_sizes, int n_in,
                              void* d_out, int out_size) {
    const float* x  = (const float*)d_in[0];
    const void*  ei = d_in[1];
    const float* W1 = (const float*)d_in[2];
    const float* b1 = (const float*)d_in[3];
    const float* W2 = (const float*)d_in[4];
    const float* b2 = (const float*)d_in[5];
    const float* Wd = (const float*)d_in[6];
    const float* bd = (const float*)d_in[7];

    const int N = in_sizes[0] / IN_F;     // 100000
    const int E = in_sizes[1] / 2;        // 1.6M

    float* out = (float*)d_out;           // x_recon [N, IN_F]
    float* z   = out + (size_t)N * IN_F;  // z       [N, OUT_F]

    __half *h0sp, *agghp, *h2sp;
    void *cntp, *statep;
    cudaGetSymbolAddress((void**)&h0sp,  g_h0s);
    cudaGetSymbolAddress((void**)&agghp, g_aggh);
    cudaGetSymbolAddress((void**)&h2sp,  g_h2s);
    cudaGetSymbolAddress(&cntp,   g_cnt);
    cudaGetSymbolAddress(&statep, g_scanstate);

    // smem (bytes): Ws2 (K/2)*(NC+8) + As2 64*(K/2+4), 4B words
    const int smem1 = ((IN_F  / 2) * (HID_F + 8) + 64 * (IN_F  / 2 + 4)) * 4;  // 52224
    const int smem2 = ((HID_F / 2) * (OUT_F + 8) + 64 * (HID_F / 2 + 4)) * 4;  // 35840
    const int smem3 = ((OUT_F / 2) * (IN_F  + 8) + 64 * (OUT_F / 2 + 4)) * 4;  // 26624
    cudaFuncSetAttribute(gemm_fp16<IN_F, HID_F, false, true, false, true>,
                         cudaFuncAttributeMaxDynamicSharedMemorySize, smem1);
    cudaFuncSetAttribute(gemm_fp16<HID_F, OUT_F, true, true, false, true>,
                         cudaFuncAttributeMaxDynamicSharedMemorySize, smem2);
    cudaFuncSetAttribute(gemm_fp16<OUT_F, IN_F, true, false, true, false>,
                         cudaFuncAttributeMaxDynamicSharedMemorySize, smem3);

    const int T = 256;
    const int nScanBlocks = (N + 255) / 256;           // 391
    const int aggGrid = (N * 32 + T - 1) / T;          // warp per node

    // zero degree counters + lookback states (memset nodes, capture-legal)
    cudaMemsetAsync(cntp, 0, (size_t)N * sizeof(int), 0);
    cudaMemsetAsync(statep, 0, (size_t)nScanBlocks * sizeof(unsigned long long), 0);

    // degree count (inline dtype detect)
    count_kernel<<<(E + T - 1) / T, T>>>((const unsigned*)ei, ei, E);

    // single-pass scan: rowptr, pos, dinv
    scan_onepass<<<nScanBlocks, 256>>>(N, E);

    // layer-1 GEMM (fp32 in, fp16 out, *dinv): h0s = (x @ W1) * dinv
    gemm_fp16<IN_F, HID_F, false, true, false, true><<<592, T, smem1>>>(
        x, W1, nullptr, h0sp, N);

    // CSR adjacency fill (inline dtype detect)
    fill_kernel<<<(E + T - 1) / T, T>>>((const unsigned*)ei, ei, E);

    // layer-1 aggregation: aggh = relu(dinv*(sum h0s + self) + b1)  (fp16)
    gather_agg<HID_F, true, 0><<<aggGrid, T>>>(h0sp, b1, agghp, nullptr, N);

    // layer-2 GEMM (fp16 in, fp16 out, *dinv): h2s = (aggh @ W2) * dinv
    gemm_fp16<HID_F, OUT_F, true, true, false, true><<<592, T, smem2>>>(
        agghp, W2, nullptr, h2sp, N);

    // layer-2 aggregation: z -> d_out (fp32) + fp16 copy into aggh for GEMM3
    gather_agg<OUT_F, false, 2><<<aggGrid, T>>>(h2sp, b2, z, agghp, N);

    // decoder (fp16 A from z16 copy, fp32 out): x_recon = z @ Wd + bd
    gemm_fp16<OUT_F, IN_F, true, false, true, false><<<592, T, smem3>>>(
        agghp, Wd, bd, out, N);
}

// round 13
// speedup vs baseline: 1.0226x; 1.0226x over previous
#include <cuda_runtime.h>
#include <cuda_fp16.h>
#include <cstdint>

#define IN_F   128
#define HID_F  128
#define OUT_F  64
#define MAX_N  100000
#define MAX_E  1600000

// ---------------- scratch (static device memory; no allocations) ----------------
__device__ float  g_dinv  [MAX_N];
__device__ int    g_cnt   [MAX_N];
__device__ int    g_rowptr[MAX_N + 1];
__device__ int    g_pos   [MAX_N];
__device__ int    g_col   [MAX_E];         // src id per CSR slot (4B)
__device__ unsigned long long g_scanstate[512];   // decoupled-lookback states
__device__ __half g_h0s   [(size_t)MAX_N * HID_F];   // (x @ W1)*dinv      (fp16)
__device__ __half g_aggh  [(size_t)MAX_N * HID_F];   // relu(conv1) / z16  (fp16)
__device__ __half g_h2s   [(size_t)MAX_N * OUT_F];   // (aggh @ W2)*dinv   (fp16)

// ---------------- inline edge-dtype detection (per-warp, no global state) --------
// int64 node ids < 1e5 -> every odd 32-bit word zero; 32-lane ballot decides.
__device__ __forceinline__ int detect_is64(const unsigned* __restrict__ w) {
    int lane = threadIdx.x & 31;
    return __ballot_sync(0xffffffffu, w[2 * lane + 1] != 0u) == 0u;
}

// 4 edges per thread; also zeroes the scan states (block 0) for the next kernel.
__global__ void count_kernel(const unsigned* __restrict__ w,
                             const void* __restrict__ ei, int E) {
    const int is64 = detect_is64(w);
    if (blockIdx.x == 0 && threadIdx.x < 512)
        g_scanstate[threadIdx.x] = 0ULL;
    int i = (blockIdx.x * blockDim.x + threadIdx.x) * 4;
    if (i >= E) return;
    int d[4];
    if (i + 3 < E) {
        if (is64) {
            const longlong2* p = (const longlong2*)((const long long*)ei + (size_t)E + i);
            longlong2 a = p[0], b = p[1];
            d[0] = (int)a.x; d[1] = (int)a.y; d[2] = (int)b.x; d[3] = (int)b.y;
        } else {
            int4 a = *(const int4*)((const int*)ei + (size_t)E + i);
            d[0] = a.x; d[1] = a.y; d[2] = a.z; d[3] = a.w;
        }
#pragma unroll
        for (int q = 0; q < 4; q++) atomicAdd(&g_cnt[d[q]], 1);
    } else {
        for (int q = 0; i + q < E; q++) {
            int dd = is64 ? (int)((const long long*)ei)[(size_t)E + i + q]
                          : ((const int*)ei)[(size_t)E + i + q];
            atomicAdd(&g_cnt[dd], 1);
        }
    }
}

// ---------------- single-pass scan (decoupled lookback) + dinv/pos ---------------
__global__ void scan_onepass(int n, int E) {
    __shared__ int sh[256];
    __shared__ int exsh;
    const int tid = threadIdx.x, b = blockIdx.x;
    const int i = b * 256 + tid;
    const int v = (i < n) ? g_cnt[i] : 0;
    sh[tid] = v;
    __syncthreads();
#pragma unroll
    for (int off = 1; off < 256; off <<= 1) {
        int t = (tid >= off) ? sh[tid - off] : 0;
        __syncthreads();
        sh[tid] += t;
        __syncthreads();
    }
    const int incl = sh[tid];
    const int aggregate = sh[255];

    if (tid == 0) {
        unsigned long long packed =
            ((b == 0 ? 2ULL : 1ULL) << 62) | (unsigned long long)(unsigned)aggregate;
        atomicExch(&g_scanstate[b], packed);
        if (b == 0) exsh = 0;
    }
    if (b != 0 && tid < 32) {
        const int lane = tid;
        unsigned long long ex = 0;
        int idx = b - 1;
        while (true) {
            int j = idx - lane;
            unsigned long long sv = (j >= 0) ? atomicAdd(&g_scanstate[j], 0ULL)
                                             : (2ULL << 62);     // virtual prefix 0
            int st = (int)(sv >> 62);
            unsigned pm = __ballot_sync(0xffffffffu, st == 2);
            unsigned im = __ballot_sync(0xffffffffu, st == 0);
            int pv = pm ? (__ffs(pm) - 1) : 32;
            int iv = im ? (__ffs(im) - 1) : 32;
            if (iv < pv) continue;                 // invalid before prefix: retry
            unsigned long long val = sv & 0x3fffffffffffffffULL;
            unsigned long long contrib = (lane <= (pv < 32 ? pv : 31)) ? val : 0;
#pragma unroll
            for (int o = 16; o; o >>= 1)
                contrib += __shfl_down_sync(0xffffffffu, contrib, o);
            contrib = __shfl_sync(0xffffffffu, contrib, 0);
            ex += contrib;
            if (pv < 32) break;
            idx -= 32;
        }
        if (lane == 0) {
            unsigned long long packed =
                (2ULL << 62) | (ex + (unsigned long long)(unsigned)aggregate);
            atomicExch(&g_scanstate[b], packed);
            exsh = (int)ex;
        }
    }
    __syncthreads();
    const int off = exsh;
    if (i < n) {
        int r = off + incl - v;                   // exclusive prefix
        g_rowptr[i] = r;
        g_pos[i] = r;
        g_dinv[i] = rsqrtf((float)v + 1.0f);
    }
    if (i == 0) g_rowptr[n] = E;
}

// 4 edges per thread, vectorized loads for both src and dst halves.
__global__ void fill_kernel(const unsigned* __restrict__ w,
                            const void* __restrict__ ei, int E) {
    const int is64 = detect_is64(w);
    int i = (blockIdx.x * blockDim.x + threadIdx.x) * 4;
    if (i >= E) return;
    int s[4], d[4];
    if (i + 3 < E) {
        if (is64) {
            const longlong2* ps = (const longlong2*)((const long long*)ei + i);
            const longlong2* pd = (const longlong2*)((const long long*)ei + (size_t)E + i);
            longlong2 sa = ps[0], sb = ps[1], da = pd[0], db = pd[1];
            s[0] = (int)sa.x; s[1] = (int)sa.y; s[2] = (int)sb.x; s[3] = (int)sb.y;
            d[0] = (int)da.x; d[1] = (int)da.y; d[2] = (int)db.x; d[3] = (int)db.y;
        } else {
            int4 sa = *(const int4*)((const int*)ei + i);
            int4 da = *(const int4*)((const int*)ei + (size_t)E + i);
            s[0] = sa.x; s[1] = sa.y; s[2] = sa.z; s[3] = sa.w;
            d[0] = da.x; d[1] = da.y; d[2] = da.z; d[3] = da.w;
        }
#pragma unroll
        for (int q = 0; q < 4; q++) {
            int idx = atomicAdd(&g_pos[d[q]], 1);
            g_col[idx] = s[q];
        }
    } else {
        for (int q = 0; i + q < E; q++) {
            int ss, dd;
            if (is64) {
                ss = (int)((const long long*)ei)[i + q];
                dd = (int)((const long long*)ei)[(size_t)E + i + q];
            } else {
                ss = ((const int*)ei)[i + q];
                dd = ((const int*)ei)[(size_t)E + i + q];
            }
            int idx = atomicAdd(&g_pos[dd], 1);
            g_col[idx] = ss;
        }
    }
}

// ---------------- FP16 tensor-core GEMM ------------------------------------------
// C[M,NC] = A[M,K] @ W[K,NC] (+bias) (optionally * dinv[row]), fp32 accumulate.
// mma.m16n8k16.f16.f16.f32. 64-row tiles; 8 warps = 2 m-groups x 4 n-groups.
template<int K, int NC, bool A_HALF, bool OUT_HALF, bool BIAS, bool SCALE_OUT>
__global__ void __launch_bounds__(256) gemm_fp16(
        const void* __restrict__ Av, const float* __restrict__ W,
        const float* __restrict__ bias, void* __restrict__ Cv, int M) {
    constexpr int KP2  = K / 2 + 4;
    constexpr int NCP2 = NC + 8;
    constexpr int NT_W = NC / 32;

    extern __shared__ unsigned sh[];
    unsigned* Ws2 = sh;                       // (K/2) * NCP2 words
    unsigned* As2 = sh + (K / 2) * NCP2;      // 64 * KP2 words

    const int tid = threadIdx.x;

    for (int i = tid; i < (K / 2) * (NC / 4); i += 256) {
        int kp = i / (NC / 4), n4 = i - kp * (NC / 4);
        float4 r0 = *(const float4*)(W + (size_t)(2 * kp) * NC + n4 * 4);
        float4 r1 = *(const float4*)(W + (size_t)(2 * kp + 1) * NC + n4 * 4);
        uint4 u;
        *(__half2*)&u.x = __floats2half2_rn(r0.x, r1.x);
        *(__half2*)&u.y = __floats2half2_rn(r0.y, r1.y);
        *(__half2*)&u.z = __floats2half2_rn(r0.z, r1.z);
        *(__half2*)&u.w = __floats2half2_rn(r0.w, r1.w);
        *(uint4*)(Ws2 + kp * NCP2 + n4 * 4) = u;
    }

    const int warp = tid >> 5, lane = tid & 31;
    const int g = lane >> 2, tg = lane & 3;
    const int mi = warp >> 2;
    const int ni = warp & 3;
    const int ntiles = (M + 63) >> 6;

    for (int tile = blockIdx.x; tile < ntiles; tile += gridDim.x) {
        const int row0 = tile << 6;
        __syncthreads();
        constexpr int K8 = K / 8;
        for (int i = tid; i < 64 * K8; i += 256) {
            int r = i / K8, c8 = i - r * K8;
            uint4 u;
            if (A_HALF) {
                const __half* A = (const __half*)Av;
                if (row0 + r < M)
                    u = *(const uint4*)(A + (size_t)(row0 + r) * K + c8 * 8);
                else
                    u = make_uint4(0, 0, 0, 0);
            } else {
                const float* A = (const float*)Av;
                float4 v0 = {0.f, 0.f, 0.f, 0.f}, v1 = {0.f, 0.f, 0.f, 0.f};
                if (row0 + r < M) {
                    v0 = *(const float4*)(A + (size_t)(row0 + r) * K + c8 * 8);
                    v1 = *(const float4*)(A + (size_t)(row0 + r) * K + c8 * 8 + 4);
                }
                *(__half2*)&u.x = __floats2half2_rn(v0.x, v0.y);
                *(__half2*)&u.y = __floats2half2_rn(v0.z, v0.w);
                *(__half2*)&u.z = __floats2half2_rn(v1.x, v1.y);
                *(__half2*)&u.w = __floats2half2_rn(v1.z, v1.w);
            }
            *(uint4*)(As2 + r * KP2 + c8 * 4) = u;
        }
        __syncthreads();

        float acc[2][NT_W][4];
#pragma unroll
        for (int ms = 0; ms < 2; ms++)
#pragma unroll
            for (int t = 0; t < NT_W; t++)
#pragma unroll
                for (int v = 0; v < 4; v++) acc[ms][t][v] = 0.f;

        const unsigned* Arow0 = As2 + (mi * 32 + g) * KP2;
        const unsigned* Arow1 = Arow0 + 16 * KP2;
#pragma unroll
        for (int kp0 = 0; kp0 < K / 2; kp0 += 8) {
            unsigned a[2][4];
            a[0][0] = Arow0[kp0 + tg];
            a[0][1] = Arow0[8 * KP2 + kp0 + tg];
            a[0][2] = Arow0[kp0 + tg + 4];
            a[0][3] = Arow0[8 * KP2 + kp0 + tg + 4];
            a[1][0] = Arow1[kp0 + tg];
            a[1][1] = Arow1[8 * KP2 + kp0 + tg];
            a[1][2] = Arow1[kp0 + tg + 4];
            a[1][3] = Arow1[8 * KP2 + kp0 + tg + 4];
#pragma unroll
            for (int t = 0; t < NT_W; t++) {
                int n0 = ni * (NT_W * 8) + t * 8;
                unsigned b0 = Ws2[(kp0 + tg) * NCP2 + n0 + g];
                unsigned b1 = Ws2[(kp0 + tg + 4) * NCP2 + n0 + g];
#pragma unroll
                for (int ms = 0; ms < 2; ms++) {
                    asm volatile(
                        "mma.sync.aligned.m16n8k16.row.col.f32.f16.f16.f32 "
                        "{%0,%1,%2,%3},{%4,%5,%6,%7},{%8,%9},{%0,%1,%2,%3};\n"
                        : "+f"(acc[ms][t][0]), "+f"(acc[ms][t][1]),
                          "+f"(acc[ms][t][2]), "+f"(acc[ms][t][3])
                        : "r"(a[ms][0]), "r"(a[ms][1]), "r"(a[ms][2]), "r"(a[ms][3]),
                          "r"(b0), "r"(b1));
                }
            }
        }

#pragma unroll
        for (int ms = 0; ms < 2; ms++) {
            const int r0 = row0 + mi * 32 + ms * 16 + g;
            const int r1 = r0 + 8;
            float s0 = 1.f, s1 = 1.f;
            if (SCALE_OUT) {
                if (r0 < M) s0 = g_dinv[r0];
                if (r1 < M) s1 = g_dinv[r1];
            }
#pragma unroll
            for (int t = 0; t < NT_W; t++) {
                int n0 = ni * (NT_W * 8) + t * 8 + 2 * tg;
                float bx = 0.f, by = 0.f;
                if (BIAS) { bx = bias[n0]; by = bias[n0 + 1]; }
                if (OUT_HALF) {
                    __half* C = (__half*)Cv;
                    if (r0 < M)
                        *(__half2*)(C + (size_t)r0 * NC + n0) = __floats2half2_rn(
                            (acc[ms][t][0] + bx) * s0, (acc[ms][t][1] + by) * s0);
                    if (r1 < M)
                        *(__half2*)(C + (size_t)r1 * NC + n0) = __floats2half2_rn(
                            (acc[ms][t][2] + bx) * s1, (acc[ms][t][3] + by) * s1);
                } else {
                    float* C = (float*)Cv;
                    if (r0 < M) {
                        float2 o = {(acc[ms][t][0] + bx) * s0, (acc[ms][t][1] + by) * s0};
                        *(float2*)(C + (size_t)r0 * NC + n0) = o;
                    }
                    if (r1 < M) {
                        float2 o = {(acc[ms][t][2] + bx) * s1, (acc[ms][t][3] + by) * s1};
                        *(float2*)(C + (size_t)r1 * NC + n0) = o;
                    }
                }
            }
        }
    }
}

// ------------- CSR gather over pre-scaled features (warp per destination row) ---
// hs[i] = h[i]*dinv[i] (fp16). out[i] = dv*(sum_nbr hs[s] + hs[i]) + bias ; relu?
// OUT_MODE: 0 = fp16 out ; 1 = fp32 out ; 2 = fp32 out + fp16 copy (out16)
template<int F, bool RELU, int OUT_MODE>
__global__ void __launch_bounds__(256) gather_agg(
        const __half* __restrict__ hs, const float* __restrict__ bias,
        void* __restrict__ out, __half* __restrict__ out16, int Nn) {
    int w = (blockIdx.x * 256 + threadIdx.x) >> 5;
    int lane = threadIdx.x & 31;
    if (w >= Nn) return;
    constexpr int V = F / 32;               // halves per lane: 4 or 2

    float dv = g_dinv[w];
    float acc[V];

    {
        const __half* hp = hs + (size_t)w * F + lane * V;
        if (V == 4) {
            uint2 u = *(const uint2*)hp;
            float2 f0 = __half22float2(*(const __half2*)&u.x);
            float2 f1 = __half22float2(*(const __half2*)&u.y);
            acc[0] = f0.x; acc[1] = f0.y; acc[2] = f1.x; acc[3] = f1.y;
        } else {
            unsigned u = *(const unsigned*)hp;
            float2 f0 = __half22float2(*(const __half2*)&u);
            acc[0] = f0.x; acc[1] = f0.y;
        }
    }

    int beg = g_rowptr[w], end = g_rowptr[w + 1];
#pragma unroll 8
    for (int j = beg; j < end; j++) {
        int s = g_col[j];                   // 4B warp-uniform broadcast load
        const __half* hp = hs + (size_t)s * F + lane * V;
        if (V == 4) {
            uint2 u = *(const uint2*)hp;
            float2 f0 = __half22float2(*(const __half2*)&u.x);
            float2 f1 = __half22float2(*(const __half2*)&u.y);
            acc[0] += f0.x; acc[1] += f0.y; acc[2] += f1.x; acc[3] += f1.y;
        } else {
            unsigned u = *(const unsigned*)hp;
            float2 f0 = __half22float2(*(const __half2*)&u);
            acc[0] += f0.x; acc[1] += f0.y;
        }
    }

    float res[V];
#pragma unroll
    for (int v = 0; v < V; v++) {
        res[v] = fmaf(acc[v], dv, bias[lane * V + v]);
        if (RELU) res[v] = fmaxf(res[v], 0.f);
    }

    if (OUT_MODE == 0) {
        __half* op = (__half*)out + (size_t)w * F + lane * V;
        if (V == 4) {
            uint2 u;
            *(__half2*)&u.x = __floats2half2_rn(res[0], res[1]);
            *(__half2*)&u.y = __floats2half2_rn(res[2], res[3]);
            *(uint2*)op = u;
        } else {
            *(__half2*)op = __floats2half2_rn(res[0], res[1]);
        }
    } else {
        float* op = (float*)out + (size_t)w * F + lane * V;
        if (V == 4) { float4 o = {res[0], res[1], res[2], res[3]}; *(float4*)op = o; }
        else        { float2 o = {res[0], res[1]};                 *(float2*)op = o; }
        if (OUT_MODE == 2) {
            __half* op16 = out16 + (size_t)w * F + lane * V;
            if (V == 4) {
                uint2 u;
                *(__half2*)&u.x = __floats2half2_rn(res[0], res[1]);
                *(__half2*)&u.y = __floats2half2_rn(res[2], res[3]);
                *(uint2*)op16 = u;
            } else {
                *(__half2*)op16 = __floats2half2_rn(res[0], res[1]);
            }
        }
    }
}

// --------------------------------- launch ---------------------------------------
extern "C" void kernel_launch(void* const* d_in, const int* in_sizes, int n_in,
                              void* d_out, int out_size) {
    const float* x  = (const float*)d_in[0];
    const void*  ei = d_in[1];
    const float* W1 = (const float*)d_in[2];
    const float* b1 = (const float*)d_in[3];
    const float* W2 = (const float*)d_in[4];
    const float* b2 = (const float*)d_in[5];
    const float* Wd = (const float*)d_in[6];
    const float* bd = (const float*)d_in[7];

    const int N = in_sizes[0] / IN_F;     // 100000
    const int E = in_sizes[1] / 2;        // 1.6M

    float* out = (float*)d_out;           // x_recon [N, IN_F]
    float* z   = out + (size_t)N * IN_F;  // z       [N, OUT_F]

    __half *h0sp, *agghp, *h2sp;
    void *cntp;
    cudaGetSymbolAddress((void**)&h0sp,  g_h0s);
    cudaGetSymbolAddress((void**)&agghp, g_aggh);
    cudaGetSymbolAddress((void**)&h2sp,  g_h2s);
    cudaGetSymbolAddress(&cntp, g_cnt);

    // smem (bytes): Ws2 (K/2)*(NC+8) + As2 64*(K/2+4), 4B words
    const int smem1 = ((IN_F  / 2) * (HID_F + 8) + 64 * (IN_F  / 2 + 4)) * 4;  // 52224
    const int smem2 = ((HID_F / 2) * (OUT_F + 8) + 64 * (HID_F / 2 + 4)) * 4;  // 35840
    const int smem3 = ((OUT_F / 2) * (IN_F  + 8) + 64 * (OUT_F / 2 + 4)) * 4;  // 26624
    cudaFuncSetAttribute(gemm_fp16<IN_F, HID_F, false, true, false, true>,
                         cudaFuncAttributeMaxDynamicSharedMemorySize, smem1);
    cudaFuncSetAttribute(gemm_fp16<HID_F, OUT_F, true, true, false, true>,
                         cudaFuncAttributeMaxDynamicSharedMemorySize, smem2);
    cudaFuncSetAttribute(gemm_fp16<OUT_F, IN_F, true, false, true, false>,
                         cudaFuncAttributeMaxDynamicSharedMemorySize, smem3);

    const int T = 256;
    const int nScanBlocks = (N + 255) / 256;           // 391
    const int aggGrid = (N * 32 + T - 1) / T;          // warp per node
    const int edgeGrid4 = (E / 4 + T - 1) / T;         // 4 edges per thread

    // zero degree counters (one memset node; scan states zeroed inside count)
    cudaMemsetAsync(cntp, 0, (size_t)N * sizeof(int), 0);

    // degree count (4 edges/thread, inline dtype detect, zeroes scan states)
    count_kernel<<<edgeGrid4, T>>>((const unsigned*)ei, ei, E);

    // single-pass scan: rowptr, pos, dinv
    scan_onepass<<<nScanBlocks, 256>>>(N, E);

    // layer-1 GEMM (fp32 in, fp16 out, *dinv): h0s = (x @ W1) * dinv
    gemm_fp16<IN_F, HID_F, false, true, false, true><<<592, T, smem1>>>(
        x, W1, nullptr, h0sp, N);

    // CSR adjacency fill (4 edges/thread, inline dtype detect)
    fill_kernel<<<edgeGrid4, T>>>((const unsigned*)ei, ei, E);

    // layer-1 aggregation: aggh = relu(dinv*(sum h0s + self) + b1)  (fp16)
    gather_agg<HID_F, true, 0><<<aggGrid, T>>>(h0sp, b1, agghp, nullptr, N);

    // layer-2 GEMM (fp16 in, fp16 out, *dinv): h2s = (aggh @ W2) * dinv
    gemm_fp16<HID_F, OUT_F, true, true, false, true><<<592, T, smem2>>>(
        agghp, W2, nullptr, h2sp, N);

    // layer-2 aggregation: z -> d_out (fp32) + fp16 copy into aggh for GEMM3
    gather_agg<OUT_F, false, 2><<<aggGrid, T>>>(h2sp, b2, z, agghp, N);

    // decoder (fp16 A from z16 copy, fp32 out): x_recon = z @ Wd + bd
    gemm_fp16<OUT_F, IN_F, true, false, true, false><<<592, T, smem3>>>(
        agghp, Wd, bd, out, N);
}

// round 14
// speedup vs baseline: 1.0235x; 1.0009x over previous
#include <cuda_runtime.h>
#include <cuda_fp16.h>
#include <cstdint>

#define IN_F   128
#define HID_F  128
#define OUT_F  64
#define MAX_N  100000
#define MAX_E  1600000

// ---------------- scratch (static device memory; no allocations) ----------------
__device__ float  g_dinv  [MAX_N];
__device__ int    g_cnt   [MAX_N];
__device__ int    g_rowptr[MAX_N + 1];
__device__ int    g_rank  [MAX_E];         // per-edge rank within dst (from count)
__device__ int    g_col   [MAX_E];         // src id per CSR slot (4B)
__device__ unsigned long long g_scanstate[512];   // decoupled-lookback states
__device__ __half g_h0s   [(size_t)MAX_N * HID_F];   // (x @ W1)*dinv      (fp16)
__device__ __half g_aggh  [(size_t)MAX_N * HID_F];   // relu(conv1) / z16  (fp16)
__device__ __half g_h2s   [(size_t)MAX_N * OUT_F];   // (aggh @ W2)*dinv   (fp16)

// ---------------- inline edge-dtype detection (per-warp, no global state) --------
// int64 node ids < 1e5 -> every odd 32-bit word zero; 32-lane ballot decides.
__device__ __forceinline__ int detect_is64(const unsigned* __restrict__ w) {
    int lane = threadIdx.x & 31;
    return __ballot_sync(0xffffffffu, w[2 * lane + 1] != 0u) == 0u;
}

// 4 edges per thread; atomic rank capture (coalesced write to g_rank);
// also zeroes the scan states (block 0) for the next kernel.
__global__ void count_kernel(const unsigned* __restrict__ w,
                             const void* __restrict__ ei, int E) {
    const int is64 = detect_is64(w);
    if (blockIdx.x == 0 && threadIdx.x < 512)
        g_scanstate[threadIdx.x] = 0ULL;
    int i = (blockIdx.x * blockDim.x + threadIdx.x) * 4;
    if (i >= E) return;
    if (i + 3 < E) {
        int d[4];
        if (is64) {
            const longlong2* p = (const longlong2*)((const long long*)ei + (size_t)E + i);
            longlong2 a = p[0], b = p[1];
            d[0] = (int)a.x; d[1] = (int)a.y; d[2] = (int)b.x; d[3] = (int)b.y;
        } else {
            int4 a = *(const int4*)((const int*)ei + (size_t)E + i);
            d[0] = a.x; d[1] = a.y; d[2] = a.z; d[3] = a.w;
        }
        int4 rk;
        rk.x = atomicAdd(&g_cnt[d[0]], 1);
        rk.y = atomicAdd(&g_cnt[d[1]], 1);
        rk.z = atomicAdd(&g_cnt[d[2]], 1);
        rk.w = atomicAdd(&g_cnt[d[3]], 1);
        *(int4*)(g_rank + i) = rk;
    } else {
        for (int q = 0; i + q < E; q++) {
            int dd = is64 ? (int)((const long long*)ei)[(size_t)E + i + q]
                          : ((const int*)ei)[(size_t)E + i + q];
            g_rank[i + q] = atomicAdd(&g_cnt[dd], 1);
        }
    }
}

// ---------------- single-pass scan (decoupled lookback) + dinv -------------------
__global__ void scan_onepass(int n, int E) {
    __shared__ int sh[256];
    __shared__ int exsh;
    const int tid = threadIdx.x, b = blockIdx.x;
    const int i = b * 256 + tid;
    const int v = (i < n) ? g_cnt[i] : 0;
    sh[tid] = v;
    __syncthreads();
#pragma unroll
    for (int off = 1; off < 256; off <<= 1) {
        int t = (tid >= off) ? sh[tid - off] : 0;
        __syncthreads();
        sh[tid] += t;
        __syncthreads();
    }
    const int incl = sh[tid];
    const int aggregate = sh[255];

    if (tid == 0) {
        unsigned long long packed =
            ((b == 0 ? 2ULL : 1ULL) << 62) | (unsigned long long)(unsigned)aggregate;
        atomicExch(&g_scanstate[b], packed);
        if (b == 0) exsh = 0;
    }
    if (b != 0 && tid < 32) {
        const int lane = tid;
        unsigned long long ex = 0;
        int idx = b - 1;
        while (true) {
            int j = idx - lane;
            unsigned long long sv = (j >= 0) ? atomicAdd(&g_scanstate[j], 0ULL)
                                             : (2ULL << 62);     // virtual prefix 0
            int st = (int)(sv >> 62);
            unsigned pm = __ballot_sync(0xffffffffu, st == 2);
            unsigned im = __ballot_sync(0xffffffffu, st == 0);
            int pv = pm ? (__ffs(pm) - 1) : 32;
            int iv = im ? (__ffs(im) - 1) : 32;
            if (iv < pv) continue;                 // invalid before prefix: retry
            unsigned long long val = sv & 0x3fffffffffffffffULL;
            unsigned long long contrib = (lane <= (pv < 32 ? pv : 31)) ? val : 0;
#pragma unroll
            for (int o = 16; o; o >>= 1)
                contrib += __shfl_down_sync(0xffffffffu, contrib, o);
            contrib = __shfl_sync(0xffffffffu, contrib, 0);
            ex += contrib;
            if (pv < 32) break;
            idx -= 32;
        }
        if (lane == 0) {
            unsigned long long packed =
                (2ULL << 62) | (ex + (unsigned long long)(unsigned)aggregate);
            atomicExch(&g_scanstate[b], packed);
            exsh = (int)ex;
        }
    }
    __syncthreads();
    const int off = exsh;
    if (i < n) {
        int r = off + incl - v;                   // exclusive prefix
        g_rowptr[i] = r;
        g_dinv[i] = rsqrtf((float)v + 1.0f);
    }
    if (i == 0) g_rowptr[n] = E;
}

// 4 edges per thread; NO atomic: idx = rowptr[dst] + rank (saved by count).
__global__ void fill_kernel(const unsigned* __restrict__ w,
                            const void* __restrict__ ei, int E) {
    const int is64 = detect_is64(w);
    int i = (blockIdx.x * blockDim.x + threadIdx.x) * 4;
    if (i >= E) return;
    if (i + 3 < E) {
        int s[4], d[4];
        if (is64) {
            const longlong2* ps = (const longlong2*)((const long long*)ei + i);
            const longlong2* pd = (const longlong2*)((const long long*)ei + (size_t)E + i);
            longlong2 sa = ps[0], sb = ps[1], da = pd[0], db = pd[1];
            s[0] = (int)sa.x; s[1] = (int)sa.y; s[2] = (int)sb.x; s[3] = (int)sb.y;
            d[0] = (int)da.x; d[1] = (int)da.y; d[2] = (int)db.x; d[3] = (int)db.y;
        } else {
            int4 sa = *(const int4*)((const int*)ei + i);
            int4 da = *(const int4*)((const int*)ei + (size_t)E + i);
            s[0] = sa.x; s[1] = sa.y; s[2] = sa.z; s[3] = sa.w;
            d[0] = da.x; d[1] = da.y; d[2] = da.z; d[3] = da.w;
        }
        int4 rk = *(const int4*)(g_rank + i);
#pragma unroll
        for (int q = 0; q < 4; q++) {
            int r = (q == 0) ? rk.x : (q == 1) ? rk.y : (q == 2) ? rk.z : rk.w;
            g_col[g_rowptr[d[q]] + r] = s[q];
        }
    } else {
        for (int q = 0; i + q < E; q++) {
            int ss, dd;
            if (is64) {
                ss = (int)((const long long*)ei)[i + q];
                dd = (int)((const long long*)ei)[(size_t)E + i + q];
            } else {
                ss = ((const int*)ei)[i + q];
                dd = ((const int*)ei)[(size_t)E + i + q];
            }
            g_col[g_rowptr[dd] + g_rank[i + q]] = ss;
        }
    }
}

// ---------------- FP16 tensor-core GEMM ------------------------------------------
// C[M,NC] = A[M,K] @ W[K,NC] (+bias) (optionally * dinv[row]), fp32 accumulate.
// mma.m16n8k16.f16.f16.f32. 64-row tiles; 8 warps = 2 m-groups x 4 n-groups.
template<int K, int NC, bool A_HALF, bool OUT_HALF, bool BIAS, bool SCALE_OUT>
__global__ void __launch_bounds__(256) gemm_fp16(
        const void* __restrict__ Av, const float* __restrict__ W,
        const float* __restrict__ bias, void* __restrict__ Cv, int M) {
    constexpr int KP2  = K / 2 + 4;
    constexpr int NCP2 = NC + 8;
    constexpr int NT_W = NC / 32;

    extern __shared__ unsigned sh[];
    unsigned* Ws2 = sh;                       // (K/2) * NCP2 words
    unsigned* As2 = sh + (K / 2) * NCP2;      // 64 * KP2 words

    const int tid = threadIdx.x;

    for (int i = tid; i < (K / 2) * (NC / 4); i += 256) {
        int kp = i / (NC / 4), n4 = i - kp * (NC / 4);
        float4 r0 = *(const float4*)(W + (size_t)(2 * kp) * NC + n4 * 4);
        float4 r1 = *(const float4*)(W + (size_t)(2 * kp + 1) * NC + n4 * 4);
        uint4 u;
        *(__half2*)&u.x = __floats2half2_rn(r0.x, r1.x);
        *(__half2*)&u.y = __floats2half2_rn(r0.y, r1.y);
        *(__half2*)&u.z = __floats2half2_rn(r0.z, r1.z);
        *(__half2*)&u.w = __floats2half2_rn(r0.w, r1.w);
        *(uint4*)(Ws2 + kp * NCP2 + n4 * 4) = u;
    }

    const int warp = tid >> 5, lane = tid & 31;
    const int g = lane >> 2, tg = lane & 3;
    const int mi = warp >> 2;
    const int ni = warp & 3;
    const int ntiles = (M + 63) >> 6;

    for (int tile = blockIdx.x; tile < ntiles; tile += gridDim.x) {
        const int row0 = tile << 6;
        __syncthreads();
        constexpr int K8 = K / 8;
        for (int i = tid; i < 64 * K8; i += 256) {
            int r = i / K8, c8 = i - r * K8;
            uint4 u;
            if (A_HALF) {
                const __half* A = (const __half*)Av;
                if (row0 + r < M)
                    u = *(const uint4*)(A + (size_t)(row0 + r) * K + c8 * 8);
                else
                    u = make_uint4(0, 0, 0, 0);
            } else {
                const float* A = (const float*)Av;
                float4 v0 = {0.f, 0.f, 0.f, 0.f}, v1 = {0.f, 0.f, 0.f, 0.f};
                if (row0 + r < M) {
                    v0 = *(const float4*)(A + (size_t)(row0 + r) * K + c8 * 8);
                    v1 = *(const float4*)(A + (size_t)(row0 + r) * K + c8 * 8 + 4);
                }
                *(__half2*)&u.x = __floats2half2_rn(v0.x, v0.y);
                *(__half2*)&u.y = __floats2half2_rn(v0.z, v0.w);
                *(__half2*)&u.z = __floats2half2_rn(v1.x, v1.y);
                *(__half2*)&u.w = __floats2half2_rn(v1.z, v1.w);
            }
            *(uint4*)(As2 + r * KP2 + c8 * 4) = u;
        }
        __syncthreads();

        float acc[2][NT_W][4];
#pragma unroll
        for (int ms = 0; ms < 2; ms++)
#pragma unroll
            for (int t = 0; t < NT_W; t++)
#pragma unroll
                for (int v = 0; v < 4; v++) acc[ms][t][v] = 0.f;

        const unsigned* Arow0 = As2 + (mi * 32 + g) * KP2;
        const unsigned* Arow1 = Arow0 + 16 * KP2;
#pragma unroll
        for (int kp0 = 0; kp0 < K / 2; kp0 += 8) {
            unsigned a[2][4];
            a[0][0] = Arow0[kp0 + tg];
            a[0][1] = Arow0[8 * KP2 + kp0 + tg];
            a[0][2] = Arow0[kp0 + tg + 4];
            a[0][3] = Arow0[8 * KP2 + kp0 + tg + 4];
            a[1][0] = Arow1[kp0 + tg];
            a[1][1] = Arow1[8 * KP2 + kp0 + tg];
            a[1][2] = Arow1[kp0 + tg + 4];
            a[1][3] = Arow1[8 * KP2 + kp0 + tg + 4];
#pragma unroll
            for (int t = 0; t < NT_W; t++) {
                int n0 = ni * (NT_W * 8) + t * 8;
                unsigned b0 = Ws2[(kp0 + tg) * NCP2 + n0 + g];
                unsigned b1 = Ws2[(kp0 + tg + 4) * NCP2 + n0 + g];
#pragma unroll
                for (int ms = 0; ms < 2; ms++) {
                    asm volatile(
                        "mma.sync.aligned.m16n8k16.row.col.f32.f16.f16.f32 "
                        "{%0,%1,%2,%3},{%4,%5,%6,%7},{%8,%9},{%0,%1,%2,%3};\n"
                        : "+f"(acc[ms][t][0]), "+f"(acc[ms][t][1]),
                          "+f"(acc[ms][t][2]), "+f"(acc[ms][t][3])
                        : "r"(a[ms][0]), "r"(a[ms][1]), "r"(a[ms][2]), "r"(a[ms][3]),
                          "r"(b0), "r"(b1));
                }
            }
        }

#pragma unroll
        for (int ms = 0; ms < 2; ms++) {
            const int r0 = row0 + mi * 32 + ms * 16 + g;
            const int r1 = r0 + 8;
            float s0 = 1.f, s1 = 1.f;
            if (SCALE_OUT) {
                if (r0 < M) s0 = g_dinv[r0];
                if (r1 < M) s1 = g_dinv[r1];
            }
#pragma unroll
            for (int t = 0; t < NT_W; t++) {
                int n0 = ni * (NT_W * 8) + t * 8 + 2 * tg;
                float bx = 0.f, by = 0.f;
                if (BIAS) { bx = bias[n0]; by = bias[n0 + 1]; }
                if (OUT_HALF) {
                    __half* C = (__half*)Cv;
                    if (r0 < M)
                        *(__half2*)(C + (size_t)r0 * NC + n0) = __floats2half2_rn(
                            (acc[ms][t][0] + bx) * s0, (acc[ms][t][1] + by) * s0);
                    if (r1 < M)
                        *(__half2*)(C + (size_t)r1 * NC + n0) = __floats2half2_rn(
                            (acc[ms][t][2] + bx) * s1, (acc[ms][t][3] + by) * s1);
                } else {
                    float* C = (float*)Cv;
                    if (r0 < M) {
                        float2 o = {(acc[ms][t][0] + bx) * s0, (acc[ms][t][1] + by) * s0};
                        *(float2*)(C + (size_t)r0 * NC + n0) = o;
                    }
                    if (r1 < M) {
                        float2 o = {(acc[ms][t][2] + bx) * s1, (acc[ms][t][3] + by) * s1};
                        *(float2*)(C + (size_t)r1 * NC + n0) = o;
                    }
                }
            }
        }
    }
}

// ------------- CSR gather over pre-scaled features (warp per destination row) ---
// hs[i] = h[i]*dinv[i] (fp16). out[i] = dv*(sum_nbr hs[s] + hs[i]) + bias ; relu?
// OUT_MODE: 0 = fp16 out ; 1 = fp32 out ; 2 = fp32 out + fp16 copy (out16)
template<int F, bool RELU, int OUT_MODE>
__global__ void __launch_bounds__(256) gather_agg(
        const __half* __restrict__ hs, const float* __restrict__ bias,
        void* __restrict__ out, __half* __restrict__ out16, int Nn) {
    int w = (blockIdx.x * 256 + threadIdx.x) >> 5;
    int lane = threadIdx.x & 31;
    if (w >= Nn) return;
    constexpr int V = F / 32;               // halves per lane: 4 or 2

    float dv = g_dinv[w];
    float acc[V];

    {
        const __half* hp = hs + (size_t)w * F + lane * V;
        if (V == 4) {
            uint2 u = *(const uint2*)hp;
            float2 f0 = __half22float2(*(const __half2*)&u.x);
            float2 f1 = __half22float2(*(const __half2*)&u.y);
            acc[0] = f0.x; acc[1] = f0.y; acc[2] = f1.x; acc[3] = f1.y;
        } else {
            unsigned u = *(const unsigned*)hp;
            float2 f0 = __half22float2(*(const __half2*)&u);
            acc[0] = f0.x; acc[1] = f0.y;
        }
    }

    int beg = g_rowptr[w], end = g_rowptr[w + 1];
#pragma unroll 8
    for (int j = beg; j < end; j++) {
        int s = g_col[j];                   // 4B warp-uniform broadcast load
        const __half* hp = hs + (size_t)s * F + lane * V;
        if (V == 4) {
            uint2 u = *(const uint2*)hp;
            float2 f0 = __half22float2(*(const __half2*)&u.x);
            float2 f1 = __half22float2(*(const __half2*)&u.y);
            acc[0] += f0.x; acc[1] += f0.y; acc[2] += f1.x; acc[3] += f1.y;
        } else {
            unsigned u = *(const unsigned*)hp;
            float2 f0 = __half22float2(*(const __half2*)&u);
            acc[0] += f0.x; acc[1] += f0.y;
        }
    }

    float res[V];
#pragma unroll
    for (int v = 0; v < V; v++) {
        res[v] = fmaf(acc[v], dv, bias[lane * V + v]);
        if (RELU) res[v] = fmaxf(res[v], 0.f);
    }

    if (OUT_MODE == 0) {
        __half* op = (__half*)out + (size_t)w * F + lane * V;
        if (V == 4) {
            uint2 u;
            *(__half2*)&u.x = __floats2half2_rn(res[0], res[1]);
            *(__half2*)&u.y = __floats2half2_rn(res[2], res[3]);
            *(uint2*)op = u;
        } else {
            *(__half2*)op = __floats2half2_rn(res[0], res[1]);
        }
    } else {
        float* op = (float*)out + (size_t)w * F + lane * V;
        if (V == 4) { float4 o = {res[0], res[1], res[2], res[3]}; *(float4*)op = o; }
        else        { float2 o = {res[0], res[1]};                 *(float2*)op = o; }
        if (OUT_MODE == 2) {
            __half* op16 = out16 + (size_t)w * F + lane * V;
            if (V == 4) {
                uint2 u;
                *(__half2*)&u.x = __floats2half2_rn(res[0], res[1]);
                *(__half2*)&u.y = __floats2half2_rn(res[2], res[3]);
                *(uint2*)op16 = u;
            } else {
                *(__half2*)op16 = __floats2half2_rn(res[0], res[1]);
            }
        }
    }
}

// --------------------------------- launch ---------------------------------------
extern "C" void kernel_launch(void* const* d_in, const int* in_sizes, int n_in,
                              void* d_out, int out_size) {
    const float* x  = (const float*)d_in[0];
    const void*  ei = d_in[1];
    const float* W1 = (const float*)d_in[2];
    const float* b1 = (const float*)d_in[3];
    const float* W2 = (const float*)d_in[4];
    const float* b2 = (const float*)d_in[5];
    const float* Wd = (const float*)d_in[6];
    const float* bd = (const float*)d_in[7];

    const int N = in_sizes[0] / IN_F;     // 100000
    const int E = in_sizes[1] / 2;        // 1.6M

    float* out = (float*)d_out;           // x_recon [N, IN_F]
    float* z   = out + (size_t)N * IN_F;  // z       [N, OUT_F]

    __half *h0sp, *agghp, *h2sp;
    void *cntp;
    cudaGetSymbolAddress((void**)&h0sp,  g_h0s);
    cudaGetSymbolAddress((void**)&agghp, g_aggh);
    cudaGetSymbolAddress((void**)&h2sp,  g_h2s);
    cudaGetSymbolAddress(&cntp, g_cnt);

    // smem (bytes): Ws2 (K/2)*(NC+8) + As2 64*(K/2+4), 4B words
    const int smem1 = ((IN_F  / 2) * (HID_F + 8) + 64 * (IN_F  / 2 + 4)) * 4;  // 52224
    const int smem2 = ((HID_F / 2) * (OUT_F + 8) + 64 * (HID_F / 2 + 4)) * 4;  // 35840
    const int smem3 = ((OUT_F / 2) * (IN_F  + 8) + 64 * (OUT_F / 2 + 4)) * 4;  // 26624
    cudaFuncSetAttribute(gemm_fp16<IN_F, HID_F, false, true, false, true>,
                         cudaFuncAttributeMaxDynamicSharedMemorySize, smem1);
    cudaFuncSetAttribute(gemm_fp16<HID_F, OUT_F, true, true, false, true>,
                         cudaFuncAttributeMaxDynamicSharedMemorySize, smem2);
    cudaFuncSetAttribute(gemm_fp16<OUT_F, IN_F, true, false, true, false>,
                         cudaFuncAttributeMaxDynamicSharedMemorySize, smem3);

    const int T = 256;
    const int nScanBlocks = (N + 255) / 256;           // 391
    const int aggGrid = (N * 32 + T - 1) / T;          // warp per node
    const int edgeGrid4 = (E / 4 + T - 1) / T;         // 4 edges per thread

    // zero degree counters (one memset node; scan states zeroed inside count)
    cudaMemsetAsync(cntp, 0, (size_t)N * sizeof(int), 0);

    // degree count + per-edge rank capture (4 edges/thread)
    count_kernel<<<edgeGrid4, T>>>((const unsigned*)ei, ei, E);

    // single-pass scan: rowptr, dinv
    scan_onepass<<<nScanBlocks, 256>>>(N, E);

    // layer-1 GEMM (fp32 in, fp16 out, *dinv): h0s = (x @ W1) * dinv
    gemm_fp16<IN_F, HID_F, false, true, false, true><<<592, T, smem1>>>(
        x, W1, nullptr, h0sp, N);

    // CSR adjacency fill (atomic-free: rowptr[d] + rank)
    fill_kernel<<<edgeGrid4, T>>>((const unsigned*)ei, ei, E);

    // layer-1 aggregation: aggh = relu(dinv*(sum h0s + self) + b1)  (fp16)
    gather_agg<HID_F, true, 0><<<aggGrid, T>>>(h0sp, b1, agghp, nullptr, N);

    // layer-2 GEMM (fp16 in, fp16 out, *dinv): h2s = (aggh @ W2) * dinv
    gemm_fp16<HID_F, OUT_F, true, true, false, true><<<592, T, smem2>>>(
        agghp, W2, nullptr, h2sp, N);

    // layer-2 aggregation: z -> d_out (fp32) + fp16 copy into aggh for GEMM3
    gather_agg<OUT_F, false, 2><<<aggGrid, T>>>(h2sp, b2, z, agghp, N);

    // decoder (fp16 A from z16 copy, fp32 out): x_recon = z @ Wd + bd
    gemm_fp16<OUT_F, IN_F, true, false, true, false><<<592, T, smem3>>>(
        agghp, Wd, bd, out, N);
}

// round 15
// speedup vs baseline: 1.0338x; 1.0100x over previous
#include <cuda_runtime.h>
#include <cuda_fp16.h>
#include <cstdint>

#define IN_F   128
#define HID_F  128
#define OUT_F  64
#define MAX_N  100000
#define MAX_E  1600000

// ---------------- scratch (static device memory; no allocations) ----------------
__device__ float  g_dinv  [MAX_N];
__device__ int    g_cnt   [MAX_N];
__device__ int    g_rowptr[MAX_N + 1];
__device__ int    g_rank  [MAX_E];         // per-edge rank within dst (from count)
__device__ int    g_col   [MAX_E];         // src id per CSR slot (4B)
__device__ unsigned long long g_scanstate[512];   // decoupled-lookback states
__device__ __half g_h0s   [(size_t)MAX_N * HID_F];   // (x @ W1)*dinv      (fp16)
__device__ __half g_aggh  [(size_t)MAX_N * HID_F];   // relu(conv1) / z16  (fp16)
__device__ __half g_h2s   [(size_t)MAX_N * OUT_F];   // (aggh @ W2)*dinv   (fp16)

// ---------------- inline edge-dtype detection (per-warp, no global state) --------
// int64 node ids < 1e5 -> every odd 32-bit word zero; 32-lane ballot decides.
__device__ __forceinline__ int detect_is64(const unsigned* __restrict__ w) {
    int lane = threadIdx.x & 31;
    return __ballot_sync(0xffffffffu, w[2 * lane + 1] != 0u) == 0u;
}

// 4 edges per thread; atomic rank capture (coalesced write to g_rank);
// also zeroes the scan states (block 0) for the next kernel.
__global__ void count_kernel(const unsigned* __restrict__ w,
                             const void* __restrict__ ei, int E) {
    const int is64 = detect_is64(w);
    if (blockIdx.x == 0 && threadIdx.x < 512)
        g_scanstate[threadIdx.x] = 0ULL;
    int i = (blockIdx.x * blockDim.x + threadIdx.x) * 4;
    if (i >= E) return;
    if (i + 3 < E) {
        int d[4];
        if (is64) {
            const longlong2* p = (const longlong2*)((const long long*)ei + (size_t)E + i);
            longlong2 a = p[0], b = p[1];
            d[0] = (int)a.x; d[1] = (int)a.y; d[2] = (int)b.x; d[3] = (int)b.y;
        } else {
            int4 a = *(const int4*)((const int*)ei + (size_t)E + i);
            d[0] = a.x; d[1] = a.y; d[2] = a.z; d[3] = a.w;
        }
        int4 rk;
        rk.x = atomicAdd(&g_cnt[d[0]], 1);
        rk.y = atomicAdd(&g_cnt[d[1]], 1);
        rk.z = atomicAdd(&g_cnt[d[2]], 1);
        rk.w = atomicAdd(&g_cnt[d[3]], 1);
        *(int4*)(g_rank + i) = rk;
    } else {
        for (int q = 0; i + q < E; q++) {
            int dd = is64 ? (int)((const long long*)ei)[(size_t)E + i + q]
                          : ((const int*)ei)[(size_t)E + i + q];
            g_rank[i + q] = atomicAdd(&g_cnt[dd], 1);
        }
    }
}

// ---------------- single-pass scan (decoupled lookback) + dinv -------------------
__global__ void scan_onepass(int n, int E) {
    __shared__ int sh[256];
    __shared__ int exsh;
    const int tid = threadIdx.x, b = blockIdx.x;
    const int i = b * 256 + tid;
    const int v = (i < n) ? g_cnt[i] : 0;
    sh[tid] = v;
    __syncthreads();
#pragma unroll
    for (int off = 1; off < 256; off <<= 1) {
        int t = (tid >= off) ? sh[tid - off] : 0;
        __syncthreads();
        sh[tid] += t;
        __syncthreads();
    }
    const int incl = sh[tid];
    const int aggregate = sh[255];

    if (tid == 0) {
        unsigned long long packed =
            ((b == 0 ? 2ULL : 1ULL) << 62) | (unsigned long long)(unsigned)aggregate;
        atomicExch(&g_scanstate[b], packed);
        if (b == 0) exsh = 0;
    }
    if (b != 0 && tid < 32) {
        const int lane = tid;
        unsigned long long ex = 0;
        int idx = b - 1;
        while (true) {
            int j = idx - lane;
            unsigned long long sv = (j >= 0) ? atomicAdd(&g_scanstate[j], 0ULL)
                                             : (2ULL << 62);     // virtual prefix 0
            int st = (int)(sv >> 62);
            unsigned pm = __ballot_sync(0xffffffffu, st == 2);
            unsigned im = __ballot_sync(0xffffffffu, st == 0);
            int pv = pm ? (__ffs(pm) - 1) : 32;
            int iv = im ? (__ffs(im) - 1) : 32;
            if (iv < pv) continue;                 // invalid before prefix: retry
            unsigned long long val = sv & 0x3fffffffffffffffULL;
            unsigned long long contrib = (lane <= (pv < 32 ? pv : 31)) ? val : 0;
#pragma unroll
            for (int o = 16; o; o >>= 1)
                contrib += __shfl_down_sync(0xffffffffu, contrib, o);
            contrib = __shfl_sync(0xffffffffu, contrib, 0);
            ex += contrib;
            if (pv < 32) break;
            idx -= 32;
        }
        if (lane == 0) {
            unsigned long long packed =
                (2ULL << 62) | (ex + (unsigned long long)(unsigned)aggregate);
            atomicExch(&g_scanstate[b], packed);
            exsh = (int)ex;
        }
    }
    __syncthreads();
    const int off = exsh;
    if (i < n) {
        int r = off + incl - v;                   // exclusive prefix
        g_rowptr[i] = r;
        g_dinv[i] = rsqrtf((float)v + 1.0f);
    }
    if (i == 0) g_rowptr[n] = E;
}

// ---------------- FP16 tensor-core GEMM ------------------------------------------
// C[M,NC] = A[M,K] @ W[K,NC] (+bias) (optionally * dinv[row]), fp32 accumulate.
// mma.m16n8k16.f16.f16.f32. 64-row tiles; 8 warps = 2 m-groups x 4 n-groups.
// FILL: grid-stride CSR-fill prologue (g_col[rowptr[d]+rank] = s) overlapped
// with the GEMM's DRAM traffic (independent work; consumer runs next kernel).
template<int K, int NC, bool A_HALF, bool OUT_HALF, bool BIAS, bool SCALE_OUT, bool FILL>
__global__ void __launch_bounds__(256) gemm_fp16(
        const void* __restrict__ Av, const float* __restrict__ W,
        const float* __restrict__ bias, void* __restrict__ Cv, int M,
        const unsigned* __restrict__ ew, const void* __restrict__ ei, int E) {
    constexpr int KP2  = K / 2 + 4;
    constexpr int NCP2 = NC + 8;
    constexpr int NT_W = NC / 32;

    extern __shared__ unsigned sh[];
    unsigned* Ws2 = sh;                       // (K/2) * NCP2 words
    unsigned* As2 = sh + (K / 2) * NCP2;      // 64 * KP2 words

    const int tid = threadIdx.x;

    for (int i = tid; i < (K / 2) * (NC / 4); i += 256) {
        int kp = i / (NC / 4), n4 = i - kp * (NC / 4);
        float4 r0 = *(const float4*)(W + (size_t)(2 * kp) * NC + n4 * 4);
        float4 r1 = *(const float4*)(W + (size_t)(2 * kp + 1) * NC + n4 * 4);
        uint4 u;
        *(__half2*)&u.x = __floats2half2_rn(r0.x, r1.x);
        *(__half2*)&u.y = __floats2half2_rn(r0.y, r1.y);
        *(__half2*)&u.z = __floats2half2_rn(r0.z, r1.z);
        *(__half2*)&u.w = __floats2half2_rn(r0.w, r1.w);
        *(uint4*)(Ws2 + kp * NCP2 + n4 * 4) = u;
    }

    // ---- fused CSR fill (independent; hidden behind GEMM's DRAM traffic) ----
    if (FILL) {
        const int is64 = detect_is64(ew);
        const int stride4 = gridDim.x * 256 * 4;
        for (int i = (blockIdx.x * 256 + tid) * 4; i < E; i += stride4) {
            if (i + 3 < E) {
                int s[4], d[4];
                if (is64) {
                    const longlong2* ps = (const longlong2*)((const long long*)ei + i);
                    const longlong2* pd = (const longlong2*)((const long long*)ei + (size_t)E + i);
                    longlong2 sa = ps[0], sb = ps[1], da = pd[0], db = pd[1];
                    s[0] = (int)sa.x; s[1] = (int)sa.y; s[2] = (int)sb.x; s[3] = (int)sb.y;
                    d[0] = (int)da.x; d[1] = (int)da.y; d[2] = (int)db.x; d[3] = (int)db.y;
                } else {
                    int4 sa = *(const int4*)((const int*)ei + i);
                    int4 da = *(const int4*)((const int*)ei + (size_t)E + i);
                    s[0] = sa.x; s[1] = sa.y; s[2] = sa.z; s[3] = sa.w;
                    d[0] = da.x; d[1] = da.y; d[2] = da.z; d[3] = da.w;
                }
                int4 rk = *(const int4*)(g_rank + i);
                g_col[g_rowptr[d[0]] + rk.x] = s[0];
                g_col[g_rowptr[d[1]] + rk.y] = s[1];
                g_col[g_rowptr[d[2]] + rk.z] = s[2];
                g_col[g_rowptr[d[3]] + rk.w] = s[3];
            } else {
                for (int q = 0; i + q < E; q++) {
                    int ss, dd;
                    if (is64) {
                        ss = (int)((const long long*)ei)[i + q];
                        dd = (int)((const long long*)ei)[(size_t)E + i + q];
                    } else {
                        ss = ((const int*)ei)[i + q];
                        dd = ((const int*)ei)[(size_t)E + i + q];
                    }
                    g_col[g_rowptr[dd] + g_rank[i + q]] = ss;
                }
            }
        }
    }

    const int warp = tid >> 5, lane = tid & 31;
    const int g = lane >> 2, tg = lane & 3;
    const int mi = warp >> 2;
    const int ni = warp & 3;
    const int ntiles = (M + 63) >> 6;

    for (int tile = blockIdx.x; tile < ntiles; tile += gridDim.x) {
        const int row0 = tile << 6;
        __syncthreads();
        constexpr int K8 = K / 8;
        for (int i = tid; i < 64 * K8; i += 256) {
            int r = i / K8, c8 = i - r * K8;
            uint4 u;
            if (A_HALF) {
                const __half* A = (const __half*)Av;
                if (row0 + r < M)
                    u = *(const uint4*)(A + (size_t)(row0 + r) * K + c8 * 8);
                else
                    u = make_uint4(0, 0, 0, 0);
            } else {
                const float* A = (const float*)Av;
                float4 v0 = {0.f, 0.f, 0.f, 0.f}, v1 = {0.f, 0.f, 0.f, 0.f};
                if (row0 + r < M) {
                    v0 = *(const float4*)(A + (size_t)(row0 + r) * K + c8 * 8);
                    v1 = *(const float4*)(A + (size_t)(row0 + r) * K + c8 * 8 + 4);
                }
                *(__half2*)&u.x = __floats2half2_rn(v0.x, v0.y);
                *(__half2*)&u.y = __floats2half2_rn(v0.z, v0.w);
                *(__half2*)&u.z = __floats2half2_rn(v1.x, v1.y);
                *(__half2*)&u.w = __floats2half2_rn(v1.z, v1.w);
            }
            *(uint4*)(As2 + r * KP2 + c8 * 4) = u;
        }
        __syncthreads();

        float acc[2][NT_W][4];
#pragma unroll
        for (int ms = 0; ms < 2; ms++)
#pragma unroll
            for (int t = 0; t < NT_W; t++)
#pragma unroll
                for (int v = 0; v < 4; v++) acc[ms][t][v] = 0.f;

        const unsigned* Arow0 = As2 + (mi * 32 + g) * KP2;
        const unsigned* Arow1 = Arow0 + 16 * KP2;
#pragma unroll
        for (int kp0 = 0; kp0 < K / 2; kp0 += 8) {
            unsigned a[2][4];
            a[0][0] = Arow0[kp0 + tg];
            a[0][1] = Arow0[8 * KP2 + kp0 + tg];
            a[0][2] = Arow0[kp0 + tg + 4];
            a[0][3] = Arow0[8 * KP2 + kp0 + tg + 4];
            a[1][0] = Arow1[kp0 + tg];
            a[1][1] = Arow1[8 * KP2 + kp0 + tg];
            a[1][2] = Arow1[kp0 + tg + 4];
            a[1][3] = Arow1[8 * KP2 + kp0 + tg + 4];
#pragma unroll
            for (int t = 0; t < NT_W; t++) {
                int n0 = ni * (NT_W * 8) + t * 8;
                unsigned b0 = Ws2[(kp0 + tg) * NCP2 + n0 + g];
                unsigned b1 = Ws2[(kp0 + tg + 4) * NCP2 + n0 + g];
#pragma unroll
                for (int ms = 0; ms < 2; ms++) {
                    asm volatile(
                        "mma.sync.aligned.m16n8k16.row.col.f32.f16.f16.f32 "
                        "{%0,%1,%2,%3},{%4,%5,%6,%7},{%8,%9},{%0,%1,%2,%3};\n"
                        : "+f"(acc[ms][t][0]), "+f"(acc[ms][t][1]),
                          "+f"(acc[ms][t][2]), "+f"(acc[ms][t][3])
                        : "r"(a[ms][0]), "r"(a[ms][1]), "r"(a[ms][2]), "r"(a[ms][3]),
                          "r"(b0), "r"(b1));
                }
            }
        }

#pragma unroll
        for (int ms = 0; ms < 2; ms++) {
            const int r0 = row0 + mi * 32 + ms * 16 + g;
            const int r1 = r0 + 8;
            float s0 = 1.f, s1 = 1.f;
            if (SCALE_OUT) {
                if (r0 < M) s0 = g_dinv[r0];
                if (r1 < M) s1 = g_dinv[r1];
            }
#pragma unroll
            for (int t = 0; t < NT_W; t++) {
                int n0 = ni * (NT_W * 8) + t * 8 + 2 * tg;
                float bx = 0.f, by = 0.f;
                if (BIAS) { bx = bias[n0]; by = bias[n0 + 1]; }
                if (OUT_HALF) {
                    __half* C = (__half*)Cv;
                    if (r0 < M)
                        *(__half2*)(C + (size_t)r0 * NC + n0) = __floats2half2_rn(
                            (acc[ms][t][0] + bx) * s0, (acc[ms][t][1] + by) * s0);
                    if (r1 < M)
                        *(__half2*)(C + (size_t)r1 * NC + n0) = __floats2half2_rn(
                            (acc[ms][t][2] + bx) * s1, (acc[ms][t][3] + by) * s1);
                } else {
                    float* C = (float*)Cv;
                    if (r0 < M) {
                        float2 o = {(acc[ms][t][0] + bx) * s0, (acc[ms][t][1] + by) * s0};
                        *(float2*)(C + (size_t)r0 * NC + n0) = o;
                    }
                    if (r1 < M) {
                        float2 o = {(acc[ms][t][2] + bx) * s1, (acc[ms][t][3] + by) * s1};
                        *(float2*)(C + (size_t)r1 * NC + n0) = o;
                    }
                }
            }
        }
    }
}

// ------------- CSR gather over pre-scaled features (warp per destination row) ---
// hs[i] = h[i]*dinv[i] (fp16). out[i] = dv*(sum_nbr hs[s] + hs[i]) + bias ; relu?
// OUT_MODE: 0 = fp16 out ; 1 = fp32 out ; 2 = fp32 out + fp16 copy (out16)
template<int F, bool RELU, int OUT_MODE>
__global__ void __launch_bounds__(256) gather_agg(
        const __half* __restrict__ hs, const float* __restrict__ bias,
        void* __restrict__ out, __half* __restrict__ out16, int Nn) {
    int w = (blockIdx.x * 256 + threadIdx.x) >> 5;
    int lane = threadIdx.x & 31;
    if (w >= Nn) return;
    constexpr int V = F / 32;               // halves per lane: 4 or 2

    float dv = g_dinv[w];
    float acc[V];

    {
        const __half* hp = hs + (size_t)w * F + lane * V;
        if (V == 4) {
            uint2 u = *(const uint2*)hp;
            float2 f0 = __half22float2(*(const __half2*)&u.x);
            float2 f1 = __half22float2(*(const __half2*)&u.y);
            acc[0] = f0.x; acc[1] = f0.y; acc[2] = f1.x; acc[3] = f1.y;
        } else {
            unsigned u = *(const unsigned*)hp;
            float2 f0 = __half22float2(*(const __half2*)&u);
            acc[0] = f0.x; acc[1] = f0.y;
        }
    }

    int beg = g_rowptr[w], end = g_rowptr[w + 1];
#pragma unroll 8
    for (int j = beg; j < end; j++) {
        int s = g_col[j];                   // 4B warp-uniform broadcast load
        const __half* hp = hs + (size_t)s * F + lane * V;
        if (V == 4) {
            uint2 u = *(const uint2*)hp;
            float2 f0 = __half22float2(*(const __half2*)&u.x);
            float2 f1 = __half22float2(*(const __half2*)&u.y);
            acc[0] += f0.x; acc[1] += f0.y; acc[2] += f1.x; acc[3] += f1.y;
        } else {
            unsigned u = *(const unsigned*)hp;
            float2 f0 = __half22float2(*(const __half2*)&u);
            acc[0] += f0.x; acc[1] += f0.y;
        }
    }

    float res[V];
#pragma unroll
    for (int v = 0; v < V; v++) {
        res[v] = fmaf(acc[v], dv, bias[lane * V + v]);
        if (RELU) res[v] = fmaxf(res[v], 0.f);
    }

    if (OUT_MODE == 0) {
        __half* op = (__half*)out + (size_t)w * F + lane * V;
        if (V == 4) {
            uint2 u;
            *(__half2*)&u.x = __floats2half2_rn(res[0], res[1]);
            *(__half2*)&u.y = __floats2half2_rn(res[2], res[3]);
            *(uint2*)op = u;
        } else {
            *(__half2*)op = __floats2half2_rn(res[0], res[1]);
        }
    } else {
        float* op = (float*)out + (size_t)w * F + lane * V;
        if (V == 4) { float4 o = {res[0], res[1], res[2], res[3]}; *(float4*)op = o; }
        else        { float2 o = {res[0], res[1]};                 *(float2*)op = o; }
        if (OUT_MODE == 2) {
            __half* op16 = out16 + (size_t)w * F + lane * V;
            if (V == 4) {
                uint2 u;
                *(__half2*)&u.x = __floats2half2_rn(res[0], res[1]);
                *(__half2*)&u.y = __floats2half2_rn(res[2], res[3]);
                *(uint2*)op16 = u;
            } else {
                *(__half2*)op16 = __floats2half2_rn(res[0], res[1]);
            }
        }
    }
}

// --------------------------------- launch ---------------------------------------
extern "C" void kernel_launch(void* const* d_in, const int* in_sizes, int n_in,
                              void* d_out, int out_size) {
    const float* x  = (const float*)d_in[0];
    const void*  ei = d_in[1];
    const float* W1 = (const float*)d_in[2];
    const float* b1 = (const float*)d_in[3];
    const float* W2 = (const float*)d_in[4];
    const float* b2 = (const float*)d_in[5];
    const float* Wd = (const float*)d_in[6];
    const float* bd = (const float*)d_in[7];

    const int N = in_sizes[0] / IN_F;     // 100000
    const int E = in_sizes[1] / 2;        // 1.6M

    float* out = (float*)d_out;           // x_recon [N, IN_F]
    float* z   = out + (size_t)N * IN_F;  // z       [N, OUT_F]

    __half *h0sp, *agghp, *h2sp;
    void *cntp;
    cudaGetSymbolAddress((void**)&h0sp,  g_h0s);
    cudaGetSymbolAddress((void**)&agghp, g_aggh);
    cudaGetSymbolAddress((void**)&h2sp,  g_h2s);
    cudaGetSymbolAddress(&cntp, g_cnt);

    // smem (bytes): Ws2 (K/2)*(NC+8) + As2 64*(K/2+4), 4B words
    const int smem1 = ((IN_F  / 2) * (HID_F + 8) + 64 * (IN_F  / 2 + 4)) * 4;  // 52224
    const int smem2 = ((HID_F / 2) * (OUT_F + 8) + 64 * (HID_F / 2 + 4)) * 4;  // 35840
    const int smem3 = ((OUT_F / 2) * (IN_F  + 8) + 64 * (OUT_F / 2 + 4)) * 4;  // 26624
    cudaFuncSetAttribute(gemm_fp16<IN_F, HID_F, false, true, false, true, true>,
                         cudaFuncAttributeMaxDynamicSharedMemorySize, smem1);
    cudaFuncSetAttribute(gemm_fp16<HID_F, OUT_F, true, true, false, true, false>,
                         cudaFuncAttributeMaxDynamicSharedMemorySize, smem2);
    cudaFuncSetAttribute(gemm_fp16<OUT_F, IN_F, true, false, true, false, false>,
                         cudaFuncAttributeMaxDynamicSharedMemorySize, smem3);

    const int T = 256;
    const int nScanBlocks = (N + 255) / 256;           // 391
    const int aggGrid = (N * 32 + T - 1) / T;          // warp per node
    const int edgeGrid4 = (E / 4 + T - 1) / T;         // 4 edges per thread

    // zero degree counters (one memset node; scan states zeroed inside count)
    cudaMemsetAsync(cntp, 0, (size_t)N * sizeof(int), 0);

    // degree count + per-edge rank capture (4 edges/thread)
    count_kernel<<<edgeGrid4, T>>>((const unsigned*)ei, ei, E);

    // single-pass scan: rowptr, dinv
    scan_onepass<<<nScanBlocks, 256>>>(N, E);

    // layer-1 GEMM (fp32 in, fp16 out, *dinv) + fused CSR fill:
    //   h0s = (x @ W1) * dinv ;  g_col[rowptr[d]+rank] = s
    gemm_fp16<IN_F, HID_F, false, true, false, true, true><<<592, T, smem1>>>(
        x, W1, nullptr, h0sp, N, (const unsigned*)ei, ei, E);

    // layer-1 aggregation: aggh = relu(dinv*(sum h0s + self) + b1)  (fp16)
    gather_agg<HID_F, true, 0><<<aggGrid, T>>>(h0sp, b1, agghp, nullptr, N);

    // layer-2 GEMM (fp16 in, fp16 out, *dinv): h2s = (aggh @ W2) * dinv
    gemm_fp16<HID_F, OUT_F, true, true, false, true, false><<<592, T, smem2>>>(
        agghp, W2, nullptr, h2sp, N, nullptr, nullptr, 0);

    // layer-2 aggregation: z -> d_out (fp32) + fp16 copy into aggh for GEMM3
    gather_agg<OUT_F, false, 2><<<aggGrid, T>>>(h2sp, b2, z, agghp, N);

    // decoder (fp16 A from z16 copy, fp32 out): x_recon = z @ Wd + bd
    gemm_fp16<OUT_F, IN_F, true, false, true, false, false><<<592, T, smem3>>>(
        agghp, Wd, bd, out, N, nullptr, nullptr, 0);
}

// round 16
// speedup vs baseline: 1.0679x; 1.0330x over previous
#include <cuda_runtime.h>
#include <cuda_fp16.h>
#include <cstdint>

#define IN_F   128
#define HID_F  128
#define OUT_F  64
#define MAX_N  100000
#define MAX_E  1600000

// ---------------- scratch (static device memory; no allocations) ----------------
__device__ float  g_dinv  [MAX_N];
__device__ int    g_cnt   [MAX_N];
__device__ int    g_rowptr[MAX_N + 1];
__device__ int    g_rank  [MAX_E];         // per-edge rank within dst (from count)
__device__ int    g_col   [MAX_E];         // src id per CSR slot (4B)
__device__ unsigned long long g_scanstate[512];   // decoupled-lookback states
__device__ __half g_h0s   [(size_t)MAX_N * HID_F];   // (x @ W1)*dinv      (fp16)
__device__ __half g_aggh  [(size_t)MAX_N * HID_F];   // relu(conv1) / z16  (fp16)
__device__ __half g_h2s   [(size_t)MAX_N * OUT_F];   // (aggh @ W2)*dinv   (fp16)

// ---------------- inline edge-dtype detection (per-warp, no global state) --------
__device__ __forceinline__ int detect_is64(const unsigned* __restrict__ w) {
    int lane = threadIdx.x & 31;
    return __ballot_sync(0xffffffffu, w[2 * lane + 1] != 0u) == 0u;
}

// 4 edges per thread; atomic rank capture; zeroes scan states (block 0).
__global__ void count_kernel(const unsigned* __restrict__ w,
                             const void* __restrict__ ei, int E) {
    const int is64 = detect_is64(w);
    if (blockIdx.x == 0 && threadIdx.x < 512)
        g_scanstate[threadIdx.x] = 0ULL;
    int i = (blockIdx.x * blockDim.x + threadIdx.x) * 4;
    if (i >= E) return;
    if (i + 3 < E) {
        int d[4];
        if (is64) {
            const longlong2* p = (const longlong2*)((const long long*)ei + (size_t)E + i);
            longlong2 a = p[0], b = p[1];
            d[0] = (int)a.x; d[1] = (int)a.y; d[2] = (int)b.x; d[3] = (int)b.y;
        } else {
            int4 a = *(const int4*)((const int*)ei + (size_t)E + i);
            d[0] = a.x; d[1] = a.y; d[2] = a.z; d[3] = a.w;
        }
        int4 rk;
        rk.x = atomicAdd(&g_cnt[d[0]], 1);
        rk.y = atomicAdd(&g_cnt[d[1]], 1);
        rk.z = atomicAdd(&g_cnt[d[2]], 1);
        rk.w = atomicAdd(&g_cnt[d[3]], 1);
        *(int4*)(g_rank + i) = rk;
    } else {
        for (int q = 0; i + q < E; q++) {
            int dd = is64 ? (int)((const long long*)ei)[(size_t)E + i + q]
                          : ((const int*)ei)[(size_t)E + i + q];
            g_rank[i + q] = atomicAdd(&g_cnt[dd], 1);
        }
    }
}

// ---------------- single-pass scan (decoupled lookback) + dinv -------------------
__global__ void scan_onepass(int n, int E) {
    __shared__ int sh[256];
    __shared__ int exsh;
    const int tid = threadIdx.x, b = blockIdx.x;
    const int i = b * 256 + tid;
    const int v = (i < n) ? g_cnt[i] : 0;
    sh[tid] = v;
    __syncthreads();
#pragma unroll
    for (int off = 1; off < 256; off <<= 1) {
        int t = (tid >= off) ? sh[tid - off] : 0;
        __syncthreads();
        sh[tid] += t;
        __syncthreads();
    }
    const int incl = sh[tid];
    const int aggregate = sh[255];

    if (tid == 0) {
        unsigned long long packed =
            ((b == 0 ? 2ULL : 1ULL) << 62) | (unsigned long long)(unsigned)aggregate;
        atomicExch(&g_scanstate[b], packed);
        if (b == 0) exsh = 0;
    }
    if (b != 0 && tid < 32) {
        const int lane = tid;
        unsigned long long ex = 0;
        int idx = b - 1;
        while (true) {
            int j = idx - lane;
            unsigned long long sv = (j >= 0) ? atomicAdd(&g_scanstate[j], 0ULL)
                                             : (2ULL << 62);     // virtual prefix 0
            int st = (int)(sv >> 62);
            unsigned pm = __ballot_sync(0xffffffffu, st == 2);
            unsigned im = __ballot_sync(0xffffffffu, st == 0);
            int pv = pm ? (__ffs(pm) - 1) : 32;
            int iv = im ? (__ffs(im) - 1) : 32;
            if (iv < pv) continue;                 // invalid before prefix: retry
            unsigned long long val = sv & 0x3fffffffffffffffULL;
            unsigned long long contrib = (lane <= (pv < 32 ? pv : 31)) ? val : 0;
#pragma unroll
            for (int o = 16; o; o >>= 1)
                contrib += __shfl_down_sync(0xffffffffu, contrib, o);
            contrib = __shfl_sync(0xffffffffu, contrib, 0);
            ex += contrib;
            if (pv < 32) break;
            idx -= 32;
        }
        if (lane == 0) {
            unsigned long long packed =
                (2ULL << 62) | (ex + (unsigned long long)(unsigned)aggregate);
            atomicExch(&g_scanstate[b], packed);
            exsh = (int)ex;
        }
    }
    __syncthreads();
    const int off = exsh;
    if (i < n) {
        int r = off + incl - v;                   // exclusive prefix
        g_rowptr[i] = r;
        g_dinv[i] = rsqrtf((float)v + 1.0f);
    }
    if (i == 0) g_rowptr[n] = E;
}

// ---------------- FP16 tensor-core GEMM ------------------------------------------
// C[M,NC] = A[M,K] @ W[K,NC] (+bias) (optionally * dinv[row]), fp32 accumulate.
// FILL: grid-stride CSR-fill prologue overlapped with the GEMM's DRAM traffic.
template<int K, int NC, bool A_HALF, bool OUT_HALF, bool BIAS, bool SCALE_OUT, bool FILL>
__global__ void __launch_bounds__(256) gemm_fp16(
        const void* __restrict__ Av, const float* __restrict__ W,
        const float* __restrict__ bias, void* __restrict__ Cv, int M,
        const unsigned* __restrict__ ew, const void* __restrict__ ei, int E) {
    constexpr int KP2  = K / 2 + 4;
    constexpr int NCP2 = NC + 8;
    constexpr int NT_W = NC / 32;

    extern __shared__ unsigned sh[];
    unsigned* Ws2 = sh;                       // (K/2) * NCP2 words
    unsigned* As2 = sh + (K / 2) * NCP2;      // 64 * KP2 words

    const int tid = threadIdx.x;

    for (int i = tid; i < (K / 2) * (NC / 4); i += 256) {
        int kp = i / (NC / 4), n4 = i - kp * (NC / 4);
        float4 r0 = *(const float4*)(W + (size_t)(2 * kp) * NC + n4 * 4);
        float4 r1 = *(const float4*)(W + (size_t)(2 * kp + 1) * NC + n4 * 4);
        uint4 u;
        *(__half2*)&u.x = __floats2half2_rn(r0.x, r1.x);
        *(__half2*)&u.y = __floats2half2_rn(r0.y, r1.y);
        *(__half2*)&u.z = __floats2half2_rn(r0.z, r1.z);
        *(__half2*)&u.w = __floats2half2_rn(r0.w, r1.w);
        *(uint4*)(Ws2 + kp * NCP2 + n4 * 4) = u;
    }

    // ---- fused CSR fill (independent; hidden behind GEMM's DRAM traffic) ----
    if (FILL) {
        const int is64 = detect_is64(ew);
        const int stride4 = gridDim.x * 256 * 4;
        for (int i = (blockIdx.x * 256 + tid) * 4; i < E; i += stride4) {
            if (i + 3 < E) {
                int s[4], d[4];
                if (is64) {
                    const longlong2* ps = (const longlong2*)((const long long*)ei + i);
                    const longlong2* pd = (const longlong2*)((const long long*)ei + (size_t)E + i);
                    longlong2 sa = ps[0], sb = ps[1], da = pd[0], db = pd[1];
                    s[0] = (int)sa.x; s[1] = (int)sa.y; s[2] = (int)sb.x; s[3] = (int)sb.y;
                    d[0] = (int)da.x; d[1] = (int)da.y; d[2] = (int)db.x; d[3] = (int)db.y;
                } else {
                    int4 sa = *(const int4*)((const int*)ei + i);
                    int4 da = *(const int4*)((const int*)ei + (size_t)E + i);
                    s[0] = sa.x; s[1] = sa.y; s[2] = sa.z; s[3] = sa.w;
                    d[0] = da.x; d[1] = da.y; d[2] = da.z; d[3] = da.w;
                }
                int4 rk = *(const int4*)(g_rank + i);
                g_col[g_rowptr[d[0]] + rk.x] = s[0];
                g_col[g_rowptr[d[1]] + rk.y] = s[1];
                g_col[g_rowptr[d[2]] + rk.z] = s[2];
                g_col[g_rowptr[d[3]] + rk.w] = s[3];
            } else {
                for (int q = 0; i + q < E; q++) {
                    int ss, dd;
                    if (is64) {
                        ss = (int)((const long long*)ei)[i + q];
                        dd = (int)((const long long*)ei)[(size_t)E + i + q];
                    } else {
                        ss = ((const int*)ei)[i + q];
                        dd = ((const int*)ei)[(size_t)E + i + q];
                    }
                    g_col[g_rowptr[dd] + g_rank[i + q]] = ss;
                }
            }
        }
    }

    const int warp = tid >> 5, lane = tid & 31;
    const int g = lane >> 2, tg = lane & 3;
    const int mi = warp >> 2;
    const int ni = warp & 3;
    const int ntiles = (M + 63) >> 6;

    for (int tile = blockIdx.x; tile < ntiles; tile += gridDim.x) {
        const int row0 = tile << 6;
        __syncthreads();
        constexpr int K8 = K / 8;
        for (int i = tid; i < 64 * K8; i += 256) {
            int r = i / K8, c8 = i - r * K8;
            uint4 u;
            if (A_HALF) {
                const __half* A = (const __half*)Av;
                if (row0 + r < M)
                    u = *(const uint4*)(A + (size_t)(row0 + r) * K + c8 * 8);
                else
                    u = make_uint4(0, 0, 0, 0);
            } else {
                const float* A = (const float*)Av;
                float4 v0 = {0.f, 0.f, 0.f, 0.f}, v1 = {0.f, 0.f, 0.f, 0.f};
                if (row0 + r < M) {
                    v0 = *(const float4*)(A + (size_t)(row0 + r) * K + c8 * 8);
                    v1 = *(const float4*)(A + (size_t)(row0 + r) * K + c8 * 8 + 4);
                }
                *(__half2*)&u.x = __floats2half2_rn(v0.x, v0.y);
                *(__half2*)&u.y = __floats2half2_rn(v0.z, v0.w);
                *(__half2*)&u.z = __floats2half2_rn(v1.x, v1.y);
                *(__half2*)&u.w = __floats2half2_rn(v1.z, v1.w);
            }
            *(uint4*)(As2 + r * KP2 + c8 * 4) = u;
        }
        __syncthreads();

        float acc[2][NT_W][4];
#pragma unroll
        for (int ms = 0; ms < 2; ms++)
#pragma unroll
            for (int t = 0; t < NT_W; t++)
#pragma unroll
                for (int v = 0; v < 4; v++) acc[ms][t][v] = 0.f;

        const unsigned* Arow0 = As2 + (mi * 32 + g) * KP2;
        const unsigned* Arow1 = Arow0 + 16 * KP2;
#pragma unroll
        for (int kp0 = 0; kp0 < K / 2; kp0 += 8) {
            unsigned a[2][4];
            a[0][0] = Arow0[kp0 + tg];
            a[0][1] = Arow0[8 * KP2 + kp0 + tg];
            a[0][2] = Arow0[kp0 + tg + 4];
            a[0][3] = Arow0[8 * KP2 + kp0 + tg + 4];
            a[1][0] = Arow1[kp0 + tg];
            a[1][1] = Arow1[8 * KP2 + kp0 + tg];
            a[1][2] = Arow1[kp0 + tg + 4];
            a[1][3] = Arow1[8 * KP2 + kp0 + tg + 4];
#pragma unroll
            for (int t = 0; t < NT_W; t++) {
                int n0 = ni * (NT_W * 8) + t * 8;
                unsigned b0 = Ws2[(kp0 + tg) * NCP2 + n0 + g];
                unsigned b1 = Ws2[(kp0 + tg + 4) * NCP2 + n0 + g];
#pragma unroll
                for (int ms = 0; ms < 2; ms++) {
                    asm volatile(
                        "mma.sync.aligned.m16n8k16.row.col.f32.f16.f16.f32 "
                        "{%0,%1,%2,%3},{%4,%5,%6,%7},{%8,%9},{%0,%1,%2,%3};\n"
                        : "+f"(acc[ms][t][0]), "+f"(acc[ms][t][1]),
                          "+f"(acc[ms][t][2]), "+f"(acc[ms][t][3])
                        : "r"(a[ms][0]), "r"(a[ms][1]), "r"(a[ms][2]), "r"(a[ms][3]),
                          "r"(b0), "r"(b1));
                }
            }
        }

#pragma unroll
        for (int ms = 0; ms < 2; ms++) {
            const int r0 = row0 + mi * 32 + ms * 16 + g;
            const int r1 = r0 + 8;
            float s0 = 1.f, s1 = 1.f;
            if (SCALE_OUT) {
                if (r0 < M) s0 = g_dinv[r0];
                if (r1 < M) s1 = g_dinv[r1];
            }
#pragma unroll
            for (int t = 0; t < NT_W; t++) {
                int n0 = ni * (NT_W * 8) + t * 8 + 2 * tg;
                float bx = 0.f, by = 0.f;
                if (BIAS) { bx = bias[n0]; by = bias[n0 + 1]; }
                if (OUT_HALF) {
                    __half* C = (__half*)Cv;
                    if (r0 < M)
                        *(__half2*)(C + (size_t)r0 * NC + n0) = __floats2half2_rn(
                            (acc[ms][t][0] + bx) * s0, (acc[ms][t][1] + by) * s0);
                    if (r1 < M)
                        *(__half2*)(C + (size_t)r1 * NC + n0) = __floats2half2_rn(
                            (acc[ms][t][2] + bx) * s1, (acc[ms][t][3] + by) * s1);
                } else {
                    float* C = (float*)Cv;
                    if (r0 < M) {
                        float2 o = {(acc[ms][t][0] + bx) * s0, (acc[ms][t][1] + by) * s0};
                        *(float2*)(C + (size_t)r0 * NC + n0) = o;
                    }
                    if (r1 < M) {
                        float2 o = {(acc[ms][t][2] + bx) * s1, (acc[ms][t][3] + by) * s1};
                        *(float2*)(C + (size_t)r1 * NC + n0) = o;
                    }
                }
            }
        }
    }
}

// ------------- CSR gather over pre-scaled features (warp per destination row) ---
// hs[i] = h[i]*dinv[i] (fp16). out[i] = dv*(sum_nbr hs[s] + hs[i]) + bias ; relu?
// Edge pairs pre-reduced in fp16 (HADD2) before fp32 accumulation: halves the
// cvt+add issue pressure (gather was measured issue/fma-bound, not BW-bound).
// OUT_MODE: 0 = fp16 out ; 1 = fp32 out ; 2 = fp32 out + fp16 copy (out16)
template<int F, bool RELU, int OUT_MODE>
__global__ void __launch_bounds__(256) gather_agg(
        const __half* __restrict__ hs, const float* __restrict__ bias,
        void* __restrict__ out, __half* __restrict__ out16, int Nn) {
    int w = (blockIdx.x * 256 + threadIdx.x) >> 5;
    int lane = threadIdx.x & 31;
    if (w >= Nn) return;
    constexpr int V = F / 32;               // halves per lane: 4 or 2

    float dv = g_dinv[w];
    float acc[V];

    // self-loop (pre-scaled row; dv applied at the end)
    {
        const __half* hp = hs + (size_t)w * F + lane * V;
        if (V == 4) {
            uint2 u = *(const uint2*)hp;
            float2 f0 = __half22float2(*(const __half2*)&u.x);
            float2 f1 = __half22float2(*(const __half2*)&u.y);
            acc[0] = f0.x; acc[1] = f0.y; acc[2] = f1.x; acc[3] = f1.y;
        } else {
            unsigned u = *(const unsigned*)hp;
            float2 f0 = __half22float2(*(const __half2*)&u);
            acc[0] = f0.x; acc[1] = f0.y;
        }
    }

    const int beg = g_rowptr[w], end = g_rowptr[w + 1];
    int j = beg;
#pragma unroll 4
    for (; j + 1 < end; j += 2) {
        int s0 = g_col[j];
        int s1 = g_col[j + 1];
        if (V == 4) {
            uint2 u0 = *(const uint2*)(hs + (size_t)s0 * F + lane * 4);
            uint2 u1 = *(const uint2*)(hs + (size_t)s1 * F + lane * 4);
            __half2 p0 = __hadd2(*(const __half2*)&u0.x, *(const __half2*)&u1.x);
            __half2 p1 = __hadd2(*(const __half2*)&u0.y, *(const __half2*)&u1.y);
            float2 f0 = __half22float2(p0);
            float2 f1 = __half22float2(p1);
            acc[0] += f0.x; acc[1] += f0.y; acc[2] += f1.x; acc[3] += f1.y;
        } else {
            unsigned u0 = *(const unsigned*)(hs + (size_t)s0 * F + lane * 2);
            unsigned u1 = *(const unsigned*)(hs + (size_t)s1 * F + lane * 2);
            __half2 p0 = __hadd2(*(const __half2*)&u0, *(const __half2*)&u1);
            float2 f0 = __half22float2(p0);
            acc[0] += f0.x; acc[1] += f0.y;
        }
    }
    if (j < end) {                          // odd tail edge
        int s = g_col[j];
        const __half* hp = hs + (size_t)s * F + lane * V;
        if (V == 4) {
            uint2 u = *(const uint2*)hp;
            float2 f0 = __half22float2(*(const __half2*)&u.x);
            float2 f1 = __half22float2(*(const __half2*)&u.y);
            acc[0] += f0.x; acc[1] += f0.y; acc[2] += f1.x; acc[3] += f1.y;
        } else {
            unsigned u = *(const unsigned*)hp;
            float2 f0 = __half22float2(*(const __half2*)&u);
            acc[0] += f0.x; acc[1] += f0.y;
        }
    }

    float res[V];
#pragma unroll
    for (int v = 0; v < V; v++) {
        res[v] = fmaf(acc[v], dv, bias[lane * V + v]);
        if (RELU) res[v] = fmaxf(res[v], 0.f);
    }

    if (OUT_MODE == 0) {
        __half* op = (__half*)out + (size_t)w * F + lane * V;
        if (V == 4) {
            uint2 u;
            *(__half2*)&u.x = __floats2half2_rn(res[0], res[1]);
            *(__half2*)&u.y = __floats2half2_rn(res[2], res[3]);
            *(uint2*)op = u;
        } else {
            *(__half2*)op = __floats2half2_rn(res[0], res[1]);
        }
    } else {
        float* op = (float*)out + (size_t)w * F + lane * V;
        if (V == 4) { float4 o = {res[0], res[1], res[2], res[3]}; *(float4*)op = o; }
        else        { float2 o = {res[0], res[1]};                 *(float2*)op = o; }
        if (OUT_MODE == 2) {
            __half* op16 = out16 + (size_t)w * F + lane * V;
            if (V == 4) {
                uint2 u;
                *(__half2*)&u.x = __floats2half2_rn(res[0], res[1]);
                *(__half2*)&u.y = __floats2half2_rn(res[2], res[3]);
                *(uint2*)op16 = u;
            } else {
                *(__half2*)op16 = __floats2half2_rn(res[0], res[1]);
            }
        }
    }
}

// --------------------------------- launch ---------------------------------------
extern "C" void kernel_launch(void* const* d_in, const int* in_sizes, int n_in,
                              void* d_out, int out_size) {
    const float* x  = (const float*)d_in[0];
    const void*  ei = d_in[1];
    const float* W1 = (const float*)d_in[2];
    const float* b1 = (const float*)d_in[3];
    const float* W2 = (const float*)d_in[4];
    const float* b2 = (const float*)d_in[5];
    const float* Wd = (const float*)d_in[6];
    const float* bd = (const float*)d_in[7];

    const int N = in_sizes[0] / IN_F;     // 100000
    const int E = in_sizes[1] / 2;        // 1.6M

    float* out = (float*)d_out;           // x_recon [N, IN_F]
    float* z   = out + (size_t)N * IN_F;  // z       [N, OUT_F]

    __half *h0sp, *agghp, *h2sp;
    void *cntp;
    cudaGetSymbolAddress((void**)&h0sp,  g_h0s);
    cudaGetSymbolAddress((void**)&agghp, g_aggh);
    cudaGetSymbolAddress((void**)&h2sp,  g_h2s);
    cudaGetSymbolAddress(&cntp, g_cnt);

    // smem (bytes): Ws2 (K/2)*(NC+8) + As2 64*(K/2+4), 4B words
    const int smem1 = ((IN_F  / 2) * (HID_F + 8) + 64 * (IN_F  / 2 + 4)) * 4;  // 52224
    const int smem2 = ((HID_F / 2) * (OUT_F + 8) + 64 * (HID_F / 2 + 4)) * 4;  // 35840
    const int smem3 = ((OUT_F / 2) * (IN_F  + 8) + 64 * (OUT_F / 2 + 4)) * 4;  // 26624
    cudaFuncSetAttribute(gemm_fp16<IN_F, HID_F, false, true, false, true, true>,
                         cudaFuncAttributeMaxDynamicSharedMemorySize, smem1);
    cudaFuncSetAttribute(gemm_fp16<HID_F, OUT_F, true, true, false, true, false>,
                         cudaFuncAttributeMaxDynamicSharedMemorySize, smem2);
    cudaFuncSetAttribute(gemm_fp16<OUT_F, IN_F, true, false, true, false, false>,
                         cudaFuncAttributeMaxDynamicSharedMemorySize, smem3);

    const int T = 256;
    const int nScanBlocks = (N + 255) / 256;           // 391
    const int aggGrid = (N * 32 + T - 1) / T;          // warp per node
    const int edgeGrid4 = (E / 4 + T - 1) / T;         // 4 edges per thread

    // zero degree counters (one memset node; scan states zeroed inside count)
    cudaMemsetAsync(cntp, 0, (size_t)N * sizeof(int), 0);

    // degree count + per-edge rank capture (4 edges/thread)
    count_kernel<<<edgeGrid4, T>>>((const unsigned*)ei, ei, E);

    // single-pass scan: rowptr, dinv
    scan_onepass<<<nScanBlocks, 256>>>(N, E);

    // layer-1 GEMM (fp32 in, fp16 out, *dinv) + fused CSR fill:
    //   h0s = (x @ W1) * dinv ;  g_col[rowptr[d]+rank] = s
    gemm_fp16<IN_F, HID_F, false, true, false, true, true><<<592, T, smem1>>>(
        x, W1, nullptr, h0sp, N, (const unsigned*)ei, ei, E);

    // layer-1 aggregation: aggh = relu(dinv*(sum h0s + self) + b1)  (fp16)
    gather_agg<HID_F, true, 0><<<aggGrid, T>>>(h0sp, b1, agghp, nullptr, N);

    // layer-2 GEMM (fp16 in, fp16 out, *dinv): h2s = (aggh @ W2) * dinv
    gemm_fp16<HID_F, OUT_F, true, true, false, true, false><<<592, T, smem2>>>(
        agghp, W2, nullptr, h2sp, N, nullptr, nullptr, 0);

    // layer-2 aggregation: z -> d_out (fp32) + fp16 copy into aggh for GEMM3
    gather_agg<OUT_F, false, 2><<<aggGrid, T>>>(h2sp, b2, z, agghp, N);

    // decoder (fp16 A from z16 copy, fp32 out): x_recon = z @ Wd + bd
    gemm_fp16<OUT_F, IN_F, true, false, true, false, false><<<592, T, smem3>>>(
        agghp, Wd, bd, out, N, nullptr, nullptr, 0);
}